// round 12
// baseline (speedup 1.0000x reference)
#include <cuda_runtime.h>
#include <cuda_fp16.h>
#include <cstdint>

// Problem constants
#define M_SUB   8
#define N_E     1024
#define E_DIM   64
#define BS_     16
#define CC_     512
#define HW_     1024
#define NPOS    16384            // BS_*HW_

// Output layout (float32)
#define OFF_ZVQ  0
#define OFF_LOSS 8388608
#define OFF_IDX  8388609
#define OFF_BIN  8519681

#define CAP   32        // candidate cap per row
#define EPSF  2e-3f     // collect threshold (>= 25x worst-case fp16 error bound)

#define CHUNK_BYTES 8448   // 16 rows x 528B (512B data + 16B pad per row)
#define NTHREADS    512

// Scratch (device globals; no allocation allowed)
__device__ float  g_esq[M_SUB * N_E];
// fp16 codebooks packed in m16n8k16 B-fragment order:
// [m][ch(16)] chunk of 16 rows (kp = ks*4+lx) x 64 uint2 (pos = gg*8+nt), row stride 528B
__device__ __align__(16) unsigned char g_cbh[M_SUB * 16 * CHUNK_BYTES];
__device__ double g_part[1024];

// ---------------- helpers ------------------------------------------------------
__device__ __forceinline__ unsigned h2u(__half2 h) {
    return *reinterpret_cast<unsigned*>(&h);
}
__device__ __forceinline__ void mma_f16(float* d, const unsigned* a,
                                        unsigned b0, unsigned b1) {
    asm volatile("mma.sync.aligned.m16n8k16.row.col.f32.f16.f16.f32 "
                 "{%0,%1,%2,%3}, {%4,%5,%6,%7}, {%8,%9}, {%0,%1,%2,%3};"
                 : "+f"(d[0]), "+f"(d[1]), "+f"(d[2]), "+f"(d[3])
                 : "r"(a[0]), "r"(a[1]), "r"(a[2]), "r"(a[3]), "r"(b0), "r"(b1));
}
__device__ __forceinline__ void cp_async16(unsigned dst, const void* src) {
    asm volatile("cp.async.cg.shared.global [%0], [%1], 16;" :: "r"(dst), "l"(src));
}
#define CP_COMMIT() asm volatile("cp.async.commit_group;")
#define CP_WAIT0()  asm volatile("cp.async.wait_group 0;" ::: "memory")

// ---------------- K0: zero bins -------------------------------------------------
__global__ void pq_init_kernel(float* __restrict__ outBins) {
    int t = threadIdx.x;
    if (t < N_E) outBins[t] = 0.0f;
}

// ---------------- K_esq: per-code squared norms (mul then sequential add) -------
__global__ void pq_esq_kernel(const float* __restrict__ cbk) {
    int t = blockIdx.x * blockDim.x + threadIdx.x;
    if (t >= M_SUB * N_E) return;
    const float* p = cbk + (size_t)t * E_DIM;
    float s = 0.0f;
    #pragma unroll
    for (int d = 0; d < E_DIM; d++) {
        float v = p[d];
        s = __fadd_rn(s, __fmul_rn(v, v));
    }
    g_esq[t] = s;
}

// ---------------- K_tr: pack codebooks into fp16 mma-fragment order -------------
// grid = 128 blocks (m x ch), 256 threads
__global__ void pq_tr_kernel(const float* __restrict__ cbk) {
    __shared__ float st[64 * 65];             // [j(code local)][k]
    int m  = blockIdx.x >> 4;
    int ch = blockIdx.x & 15;
    int tid = threadIdx.x;
    const float* src = cbk + ((size_t)(m * N_E) + ch * 64) * E_DIM;
    #pragma unroll
    for (int it = 0; it < 4; it++) {
        int i = tid + it * 256;               // 0..1023 float4 slots
        int j = i >> 4, k4 = (i & 15) * 4;
        float4 v = *(const float4*)(src + (size_t)j * E_DIM + k4);
        float* dp = st + j * 65 + k4;
        dp[0] = v.x; dp[1] = v.y; dp[2] = v.z; dp[3] = v.w;
    }
    __syncthreads();
    uint2* dst = (uint2*)(g_cbh + (size_t)(m * 16 + ch) * CHUNK_BYTES);
    #pragma unroll
    for (int it = 0; it < 4; it++) {
        int idx = tid + it * 256;             // 0..1023
        int kp = idx >> 6, pos = idx & 63;
        int gg = pos >> 3, nt = pos & 7;
        int j = nt * 8 + gg;                  // code local index
        int k0 = (kp >> 2) * 16 + (kp & 3) * 2;
        const float* r = st + j * 65;
        uint2 v;
        v.x = h2u(__floats2half2_rn(r[k0],     r[k0 + 1]));
        v.y = h2u(__floats2half2_rn(r[k0 + 8], r[k0 + 9]));
        dst[kp * 66 + pos] = v;               // row stride 528B = 66 uint2
    }
}

// ---------------- K1: fp16 MMA scoring + exact rescore + fused epilogue ---------
// Block 512 threads (16 warps). Tile: 128 rows x 1024 codes. grid = (128, 8).
// Warp w: rows (w&7)*16..+16, code-half (w>>3) (32 codes of each 64-chunk).
// smem carve (floats):
#define S_ZT    0            // z tile [128][65]            (8320)
#define S_SPB   8320         // B dbl-buf 2 x 2112          (4224)
#define S_CAND  12544        // candidates [128][CAP] int   (4096)
#define S_ESQ   16640        // esq                         (1024)
#define S_ZSQ   17664        // zsq                         (128)
#define S_CNT   17792        // counters int                (128)
#define S_WIN   17920        // winners int                 (128)
#define S_RBD   18048        // rescore partial d           (512)
#define S_RBI   18560        // rescore partial idx int     (512)
#define S_TOT   19072        // 76288 bytes
#define S_SQ    8320         // gather overlay (8320 = 4224+4096)

__global__ void __launch_bounds__(NTHREADS, 2)
pq_dist_kernel(const float* __restrict__ z,
               const float* __restrict__ cbk,
               float* __restrict__ outZvq,
               float* __restrict__ outIdx,
               float* __restrict__ outBins)
{
    extern __shared__ float sm[];
    float*    szt  = sm + S_ZT;
    float*    spb  = sm + S_SPB;
    int*      scand= (int*)(sm + S_CAND);
    float*    sesq = sm + S_ESQ;
    float*    szsq = sm + S_ZSQ;
    int*      scnt = (int*)(sm + S_CNT);
    int*      swin = (int*)(sm + S_WIN);
    float*    rbd  = sm + S_RBD;
    int*      rbi  = (int*)(sm + S_RBI);
    __shared__ double swarp[16];

    const int m  = blockIdx.y;
    const int n0 = blockIdx.x * 128;
    const int b  = n0 >> 10;
    const int p0 = n0 & 1023;
    const int tid  = threadIdx.x;
    const int wid  = tid >> 5;
    const int lane = tid & 31;
    const int gg   = lane >> 2;          // group id 0..7
    const int lx   = lane & 3;           // thread-in-group
    const int h    = wid >> 3;           // code half 0/1
    const int row0 = (wid & 7) * 16 + gg;
    const float INFF = __int_as_float(0x7f800000);

    // ---- load z tile [pos][d] (transpose from gmem [d][pos]) ----
    const float* zbase = z + ((size_t)(b * CC_ + m * E_DIM) * HW_) + p0;
    #pragma unroll
    for (int it = 0; it < 4; it++) {
        int i = tid + it * NTHREADS;
        int d = i >> 5, j4 = (i & 31) * 4;
        float4 v = *(const float4*)(zbase + (size_t)d * HW_ + j4);
        szt[(j4 + 0) * 65 + d] = v.x;
        szt[(j4 + 1) * 65 + d] = v.y;
        szt[(j4 + 2) * 65 + d] = v.z;
        szt[(j4 + 3) * 65 + d] = v.w;
    }
    #pragma unroll
    for (int it = 0; it < 2; it++)
        sesq[tid + it * NTHREADS] = g_esq[m * N_E + tid + it * NTHREADS];
    if (tid < 128) scnt[tid] = 0;

    // ---- prologue: async-load chunk 0 into buffer 0 (chunk contiguous 8448B) ----
    unsigned spb_u32 = (unsigned)__cvta_generic_to_shared(spb);
    const unsigned char* gchunk = g_cbh + (size_t)(m * 16) * CHUNK_BYTES;
    for (int i = tid; i < 528; i += NTHREADS)
        cp_async16(spb_u32 + i * 16, gchunk + i * 16);
    CP_COMMIT(); CP_WAIT0();
    __syncthreads();

    // ---- per-row ||z||^2 (sequential chain, matches reference) ----
    if (tid < 128) {
        float s = 0.0f;
        const float* zr = szt + tid * 65;
        #pragma unroll
        for (int k = 0; k < E_DIM; k++)
            s = __fadd_rn(s, __fmul_rn(zr[k], zr[k]));
        szsq[tid] = s;
    }

    // ---- A fragments fp16 (held in regs): rows row0/row0+8, k=64 ----
    unsigned afr[4][4];
    {
        const float* zr0 = szt + row0 * 65;
        const float* zr1 = szt + (row0 + 8) * 65;
        #pragma unroll
        for (int ks = 0; ks < 4; ks++) {
            int k0 = 16 * ks + 2 * lx;
            afr[ks][0] = h2u(__floats2half2_rn(zr0[k0],     zr0[k0 + 1]));
            afr[ks][1] = h2u(__floats2half2_rn(zr1[k0],     zr1[k0 + 1]));
            afr[ks][2] = h2u(__floats2half2_rn(zr0[k0 + 8], zr0[k0 + 9]));
            afr[ks][3] = h2u(__floats2half2_rn(zr1[k0 + 8], zr1[k0 + 9]));
        }
    }

    #define PUSH(rw, cc) { int p_ = atomicAdd(scnt + (rw), 1); \
                           if (p_ < CAP) scand[(rw) * CAP + p_] = (cc); }

    // ---- 16 chunks of 64 codes; this warp handles 32 codes (half h) ----
    float thr0 = INFF, thr1 = INFF;   // lagged thresholds for rows row0, row0+8
    for (int ch = 0; ch < 16; ch++) {
        const float* cur = spb + (ch & 1) * 2112;
        if (ch < 15) {
            unsigned nxt = spb_u32 + ((ch + 1) & 1) * CHUNK_BYTES;
            const unsigned char* gsrc = gchunk + (ch + 1) * CHUNK_BYTES;
            for (int i = tid; i < 528; i += NTHREADS)
                cp_async16(nxt + i * 16, gsrc + i * 16);
            CP_COMMIT();
        }

        float acc[4][4];
        #pragma unroll
        for (int a = 0; a < 4; a++)
            #pragma unroll
            for (int q = 0; q < 4; q++) acc[a][q] = 0.0f;

        const float* bp = cur + lx * 132 + gg * 16;   // row kp=ks*4+lx, col group gg
        #pragma unroll
        for (int ks = 0; ks < 4; ks++) {
            const uint4* b4 = (const uint4*)(bp + ks * 528);
            uint4 b0 = b4[h * 2];
            uint4 b1 = b4[h * 2 + 1];
            mma_f16(acc[0], afr[ks], b0.x, b0.y);
            mma_f16(acc[1], afr[ks], b0.z, b0.w);
            mma_f16(acc[2], afr[ks], b1.x, b1.y);
            mma_f16(acc[3], afr[ks], b1.z, b1.w);
        }

        // scores: esq[c] - 2*dot; codes for acc[a] = ch*64 + h*32 + a*8 + 2lx, +1
        const int cb0 = ch * 64 + h * 32 + 2 * lx;
        float m0 = INFF, m1 = INFF;
        if (ch == 0) {
            // two-pass for first chunk (no valid lagged threshold yet)
            #pragma unroll
            for (int a = 0; a < 4; a++) {
                int c = cb0 + a * 8;
                float e0 = sesq[c], e1 = sesq[c + 1];
                m0 = fminf(m0, fminf(__fmaf_rn(acc[a][0], -2.0f, e0),
                                     __fmaf_rn(acc[a][1], -2.0f, e1)));
                m1 = fminf(m1, fminf(__fmaf_rn(acc[a][2], -2.0f, e0),
                                     __fmaf_rn(acc[a][3], -2.0f, e1)));
            }
            #pragma unroll
            for (int off = 1; off <= 2; off <<= 1) {
                m0 = fminf(m0, __shfl_xor_sync(0xffffffffu, m0, off));
                m1 = fminf(m1, __shfl_xor_sync(0xffffffffu, m1, off));
            }
            thr0 = m0 + EPSF;
            thr1 = m1 + EPSF;
            #pragma unroll
            for (int a = 0; a < 4; a++) {
                int c = cb0 + a * 8;
                float e0 = sesq[c], e1 = sesq[c + 1];
                float s0 = __fmaf_rn(acc[a][0], -2.0f, e0);
                float s1 = __fmaf_rn(acc[a][1], -2.0f, e1);
                float s2 = __fmaf_rn(acc[a][2], -2.0f, e0);
                float s3 = __fmaf_rn(acc[a][3], -2.0f, e1);
                if (s0 <= thr0) PUSH(row0, c);
                if (s1 <= thr0) PUSH(row0, c + 1);
                if (s2 <= thr1) PUSH(row0 + 8, c);
                if (s3 <= thr1) PUSH(row0 + 8, c + 1);
            }
        } else {
            // single pass, lagged threshold (safe: 2*err << EPSF)
            #pragma unroll
            for (int a = 0; a < 4; a++) {
                int c = cb0 + a * 8;
                float e0 = sesq[c], e1 = sesq[c + 1];
                float s0 = __fmaf_rn(acc[a][0], -2.0f, e0);
                float s1 = __fmaf_rn(acc[a][1], -2.0f, e1);
                float s2 = __fmaf_rn(acc[a][2], -2.0f, e0);
                float s3 = __fmaf_rn(acc[a][3], -2.0f, e1);
                if (s0 <= thr0) PUSH(row0, c);
                if (s1 <= thr0) PUSH(row0, c + 1);
                if (s2 <= thr1) PUSH(row0 + 8, c);
                if (s3 <= thr1) PUSH(row0 + 8, c + 1);
                m0 = fminf(m0, fminf(s0, s1));
                m1 = fminf(m1, fminf(s2, s3));
            }
            #pragma unroll
            for (int off = 1; off <= 2; off <<= 1) {
                m0 = fminf(m0, __shfl_xor_sync(0xffffffffu, m0, off));
                m1 = fminf(m1, __shfl_xor_sync(0xffffffffu, m1, off));
            }
            thr0 = fminf(thr0, m0 + EPSF);
            thr1 = fminf(thr1, m1 + EPSF);
        }

        if (ch < 15) CP_WAIT0();
        __syncthreads();
    }

    // ---- exact rescore (reference-identical fp32 chains); 4 threads per row ----
    {
        int row = tid & 127;
        int start = tid >> 7;                 // 0..3
        int cnt = scnt[row];
        const float* zr = szt + row * 65;
        float zsqv = szsq[row];
        const float* cbm = cbk + (size_t)m * N_E * E_DIM;
        float bd = INFF; int bi = 0x7fffffff;

        auto exact_d = [&](int c) -> float {
            const float* cr = cbm + (size_t)c * E_DIM;
            float s = 0.0f;
            #pragma unroll 4
            for (int k = 0; k < E_DIM; k += 4) {
                float4 cv = *(const float4*)(cr + k);
                s = __fmaf_rn(zr[k],     cv.x, s);
                s = __fmaf_rn(zr[k + 1], cv.y, s);
                s = __fmaf_rn(zr[k + 2], cv.z, s);
                s = __fmaf_rn(zr[k + 3], cv.w, s);
            }
            return __fsub_rn(__fadd_rn(zsqv, sesq[c]), __fmul_rn(2.0f, s));
        };

        if (cnt <= CAP) {
            for (int i = start; i < cnt; i += 4) {
                int c = scand[row * CAP + i];
                float d = exact_d(c);
                if (d < bd || (d == bd && c < bi)) { bd = d; bi = c; }
            }
        } else {  // overflow fallback: full exact scan (provably correct, ~never)
            for (int c = start; c < N_E; c += 4) {
                float d = exact_d(c);
                if (d < bd || (d == bd && c < bi)) { bd = d; bi = c; }
            }
        }
        rbd[tid] = bd; rbi[tid] = bi;
    }
    __syncthreads();
    if (tid < 128) {
        float bd = rbd[tid]; int bi = rbi[tid];
        #pragma unroll
        for (int t = 1; t < 4; t++) {
            float dv = rbd[tid + 128 * t]; int iv = rbi[tid + 128 * t];
            if (dv < bd || (dv == bd && iv < bi)) { bd = dv; bi = iv; }
        }
        swin[tid] = bi;
        outIdx[m * NPOS + n0 + tid] = (float)bi;
        atomicAdd(outBins + bi, 1.0f);   // integer-valued float adds: exact
    }
    __syncthreads();

    // ---- gather winning code rows into sq[row][d], stride 65 (overlay) ----
    float* sq = sm + S_SQ;
    const float* cbm = cbk + (size_t)m * N_E * E_DIM;
    #pragma unroll
    for (int it = 0; it < 4; it++) {
        int i = tid + it * NTHREADS;
        int row = i >> 4, d4 = (i & 15) * 4;
        int idx = swin[row];
        float4 v = *(const float4*)(cbm + (size_t)idx * E_DIM + d4);
        float* dp = sq + row * 65 + d4;
        dp[0] = v.x; dp[1] = v.y; dp[2] = v.z; dp[3] = v.w;
    }
    __syncthreads();

    // ---- z_vq = zf + (zq - zf); loss partial in double ----
    double lsum = 0.0;
    float* ob = outZvq + ((size_t)(b * CC_ + m * E_DIM)) * HW_ + p0;
    #pragma unroll
    for (int it = 0; it < 4; it++) {
        int i = tid + it * NTHREADS;
        int d = i >> 5, j4 = (i & 31) * 4;
        float o[4];
        #pragma unroll
        for (int q = 0; q < 4; q++) {
            float zf = szt[(j4 + q) * 65 + d];
            float zq = sq[(j4 + q) * 65 + d];
            float df = __fsub_rn(zq, zf);
            o[q] = __fadd_rn(zf, df);
            lsum += (double)df * (double)df;
        }
        *(float4*)(ob + (size_t)d * HW_ + j4) = make_float4(o[0], o[1], o[2], o[3]);
    }

    #pragma unroll
    for (int off = 16; off > 0; off >>= 1)
        lsum += __shfl_down_sync(0xffffffffu, lsum, off);
    if (lane == 0) swarp[wid] = lsum;
    __syncthreads();
    if (wid == 0) {
        double v = (lane < 16) ? swarp[lane] : 0.0;
        #pragma unroll
        for (int off = 8; off > 0; off >>= 1)
            v += __shfl_down_sync(0xffffffffu, v, off);
        if (lane == 0) g_part[m * 128 + blockIdx.x] = v;
    }
}

// ---------------- K3: finalize loss ---------------------------------------------
__global__ void pq_loss_kernel(float* __restrict__ outLoss) {
    __shared__ double sred[256];
    int t = threadIdx.x;
    double s = 0.0;
    for (int i = t; i < 1024; i += 256) s += g_part[i];
    sred[t] = s;
    __syncthreads();
    for (int off = 128; off > 0; off >>= 1) {
        if (t < off) sred[t] += sred[t + off];
        __syncthreads();
    }
    if (t == 0) {
        double loss = 1.25 * sred[0] / (double)((size_t)NPOS * E_DIM);
        outLoss[0] = (float)loss;
    }
}

// ---------------- launch ----------------------------------------------------------
extern "C" void kernel_launch(void* const* d_in, const int* in_sizes, int n_in,
                              void* d_out, int out_size)
{
    const float* z   = (const float*)d_in[0];
    const float* cbk = (const float*)d_in[1];
    if (n_in >= 2 && in_sizes[0] == M_SUB * N_E * E_DIM) {  // swapped-order safety
        z   = (const float*)d_in[1];
        cbk = (const float*)d_in[0];
    }
    float* out = (float*)d_out;
    float* outZvq  = out + OFF_ZVQ;
    float* outLoss = out + OFF_LOSS;
    float* outIdx  = out + OFF_IDX;
    float* outBins = out + OFF_BIN;

    const int dyn_smem = S_TOT * 4;   // 76288 B
    cudaFuncSetAttribute(pq_dist_kernel,
                         cudaFuncAttributeMaxDynamicSharedMemorySize, dyn_smem);

    pq_init_kernel<<<1, 1024>>>(outBins);
    pq_esq_kernel<<<(M_SUB * N_E + 255) / 256, 256>>>(cbk);
    pq_tr_kernel<<<128, 256>>>(cbk);
    dim3 g1(NPOS / 128, M_SUB);
    pq_dist_kernel<<<g1, NTHREADS, dyn_smem>>>(z, cbk, outZvq, outIdx, outBins);
    pq_loss_kernel<<<1, 256>>>(outLoss);
}

// round 13
// speedup vs baseline: 1.5334x; 1.5334x over previous
#include <cuda_runtime.h>
#include <cstdint>

// Problem constants
#define M_SUB   8
#define N_E     1024
#define E_DIM   64
#define BS_     16
#define CC_     512
#define HW_     1024
#define NPOS    16384            // BS_*HW_

// Output layout (float32)
#define OFF_ZVQ  0
#define OFF_LOSS 8388608
#define OFF_IDX  8388609
#define OFF_BIN  8519681

#define CAP   32        // candidate cap per row
#define EPSF  2e-3f     // collect threshold (>= 3x worst-case tf32 error bound)

// Scratch (device globals; no allocation allowed)
__device__ float  g_esq[M_SUB * N_E];
__device__ float  g_cbt[M_SUB * E_DIM * N_E];   // transposed codebooks [m][k][code]
__device__ double g_part[1024];

// ---------------- helpers ------------------------------------------------------
__device__ __forceinline__ void mma_tf32(float& d0, float& d1, float& d2, float& d3,
                                         unsigned a0, unsigned a1, unsigned a2, unsigned a3,
                                         unsigned b0, unsigned b1) {
    asm volatile("mma.sync.aligned.m16n8k8.row.col.f32.tf32.tf32.f32 "
                 "{%0,%1,%2,%3}, {%4,%5,%6,%7}, {%8,%9}, {%0,%1,%2,%3};"
                 : "+f"(d0), "+f"(d1), "+f"(d2), "+f"(d3)
                 : "r"(a0), "r"(a1), "r"(a2), "r"(a3), "r"(b0), "r"(b1));
}

// ---------------- K0: zero bins -------------------------------------------------
__global__ void pq_init_kernel(float* __restrict__ outBins) {
    int t = threadIdx.x;
    if (t < N_E) outBins[t] = 0.0f;
}

// ---------------- K_esq: per-code squared norms (mul then sequential add) -------
__global__ void pq_esq_kernel(const float* __restrict__ cbk) {
    int t = blockIdx.x * blockDim.x + threadIdx.x;
    if (t >= M_SUB * N_E) return;
    const float* p = cbk + (size_t)t * E_DIM;
    float s = 0.0f;
    #pragma unroll
    for (int d = 0; d < E_DIM; d++) {
        float v = p[d];
        s = __fadd_rn(s, __fmul_rn(v, v));
    }
    g_esq[t] = s;
}

// ---------------- K_tr: transpose codebooks to k-major --------------------------
__global__ void pq_tr_kernel(const float* __restrict__ cbk) {
    __shared__ float st[64 * 128];
    int m  = blockIdx.x >> 3;
    int ct = (blockIdx.x & 7) * 128;
    int tid = threadIdx.x;
    int code = tid >> 1;
    int kh = (tid & 1) * 32;
    const float* src = cbk + ((size_t)(m * N_E) + ct + code) * E_DIM + kh;
    #pragma unroll
    for (int q = 0; q < 8; q++) {
        float4 v = *(const float4*)(src + q * 4);
        st[(kh + q * 4 + 0) * 128 + code] = v.x;
        st[(kh + q * 4 + 1) * 128 + code] = v.y;
        st[(kh + q * 4 + 2) * 128 + code] = v.z;
        st[(kh + q * 4 + 3) * 128 + code] = v.w;
    }
    __syncthreads();
    float* dst = g_cbt + (size_t)m * E_DIM * N_E + ct;
    #pragma unroll
    for (int it = 0; it < 8; it++) {
        int i = tid + it * 256;
        int k = i >> 5, c4 = (i & 31) * 4;
        *(float4*)(dst + (size_t)k * N_E + c4) = *(const float4*)(st + k * 128 + c4);
    }
}

// ---------------- K1: tf32 MMA scoring + exact rescore + fused epilogue ---------
// Block 256 threads (8 warps). Tile: 128 rows x 1024 codes. grid = (128, 8).
// smem carve (floats):
#define S_ZT    0            // z tile [128][73]           (9344)
#define S_CB    9344         // codebook chunk [64][72]    (4608)
#define S_CAND  13952        // candidates [128][CAP] int  (4096)
#define S_ESQ   18048        // esq                        (1024)
#define S_ZSQ   19072        // zsq                        (128)
#define S_CNT   19200        // counters int               (128)
#define S_PAD   19328        // (unused, keeps layout)     (128)
#define S_WIN   19456        // winners int                (128)
#define S_RBD   19584        // rescore partial d          (256)
#define S_RBI   19840        // rescore partial idx int    (256)
#define S_TOT   20096        // 80384 bytes
#define S_SQ    9344         // gather overlay (needs 8320 <= 4608+4096)

__global__ void __launch_bounds__(256, 2)
pq_dist_kernel(const float* __restrict__ z,
               const float* __restrict__ cbk,
               float* __restrict__ outZvq,
               float* __restrict__ outIdx,
               float* __restrict__ outBins)
{
    extern __shared__ float sm[];
    float*    szt  = sm + S_ZT;
    float*    scb  = sm + S_CB;
    int*      scand= (int*)(sm + S_CAND);
    float*    sesq = sm + S_ESQ;
    float*    szsq = sm + S_ZSQ;
    int*      scnt = (int*)(sm + S_CNT);
    int*      swin = (int*)(sm + S_WIN);
    float*    rbd  = sm + S_RBD;
    int*      rbi  = (int*)(sm + S_RBI);
    __shared__ double swarp[8];

    const int m  = blockIdx.y;
    const int n0 = blockIdx.x * 128;
    const int b  = n0 >> 10;
    const int p0 = n0 & 1023;
    const int tid  = threadIdx.x;
    const int wid  = tid >> 5;
    const int lane = tid & 31;
    const int gg   = lane >> 2;      // group id 0..7
    const int lx   = lane & 3;       // thread-in-group
    const int row0 = wid * 16 + gg;  // rows owned by this thread's D frags (warp-exclusive)
    const float INFF = __int_as_float(0x7f800000);

    // ---- load z tile [pos][d] (transpose from gmem [d][pos]) ----
    const float* zbase = z + ((size_t)(b * CC_ + m * E_DIM) * HW_) + p0;
    #pragma unroll
    for (int it = 0; it < 8; it++) {
        int i = tid + it * 256;
        int d = i >> 5, j4 = (i & 31) * 4;
        float4 v = *(const float4*)(zbase + (size_t)d * HW_ + j4);
        szt[(j4 + 0) * 73 + d] = v.x;
        szt[(j4 + 1) * 73 + d] = v.y;
        szt[(j4 + 2) * 73 + d] = v.z;
        szt[(j4 + 3) * 73 + d] = v.w;
    }
    #pragma unroll
    for (int it = 0; it < 4; it++)
        sesq[tid + it * 256] = g_esq[m * N_E + tid + it * 256];
    if (tid < 128) scnt[tid] = 0;
    __syncthreads();

    // ---- per-row ||z||^2 (sequential chain, matches reference) ----
    if (tid < 128) {
        float s = 0.0f;
        const float* zr = szt + tid * 73;
        #pragma unroll
        for (int k = 0; k < E_DIM; k++)
            s = __fadd_rn(s, __fmul_rn(zr[k], zr[k]));
        szsq[tid] = s;
    }

    // ---- A fragments (held in regs for whole kernel): rows row0/row0+8, k=64 ----
    unsigned afr[8][4];
    {
        const float* za = szt + row0 * 73 + lx;
        const float* zb = szt + (row0 + 8) * 73 + lx;
        #pragma unroll
        for (int ks = 0; ks < 8; ks++) {
            afr[ks][0] = __float_as_uint(za[8 * ks]);
            afr[ks][1] = __float_as_uint(zb[8 * ks]);
            afr[ks][2] = __float_as_uint(za[8 * ks + 4]);
            afr[ks][3] = __float_as_uint(zb[8 * ks + 4]);
        }
    }

    #define PUSH(rw, cc) { int p_ = atomicAdd(scnt + (rw), 1); \
                           if (p_ < CAP) scand[(rw) * CAP + p_] = (cc); }

    // ---- 16 chunks of 64 codes: MMA -> single-pass score/collect (lagged thr) --
    const float* ctb = g_cbt + (size_t)m * (E_DIM * N_E);
    float rmin0 = INFF, rmin1 = INFF;       // register prefix minima (rows warp-excl.)
    float thr0  = INFF, thr1  = INFF;
    for (int ch = 0; ch < 16; ch++) {
        __syncthreads();   // prev chunk fully consumed
        #pragma unroll
        for (int it = 0; it < 4; it++) {
            int i = tid + it * 256;
            int k = i >> 4, n4 = (i & 15) * 4;
            float4 v = *(const float4*)(ctb + (size_t)k * N_E + ch * 64 + n4);
            *(float4*)(scb + k * 72 + n4) = v;
        }
        __syncthreads();   // chunk ready

        float acc[8][4];
        #pragma unroll
        for (int nt = 0; nt < 8; nt++)
            #pragma unroll
            for (int q = 0; q < 4; q++) acc[nt][q] = 0.0f;

        const float* bp = scb + lx * 72 + gg;
        #pragma unroll
        for (int ks = 0; ks < 8; ks++) {
            #pragma unroll
            for (int nt = 0; nt < 8; nt++) {
                unsigned b0 = __float_as_uint(bp[ks * 576 + nt * 8]);
                unsigned b1 = __float_as_uint(bp[ks * 576 + 288 + nt * 8]);
                mma_tf32(acc[nt][0], acc[nt][1], acc[nt][2], acc[nt][3],
                         afr[ks][0], afr[ks][1], afr[ks][2], afr[ks][3], b0, b1);
            }
        }

        // scores: esq[c] - 2*dot ; code for acc[nt][0/2] = ch*64+nt*8+2lx, [1/3] +1
        float m0 = INFF, m1 = INFF;
        if (ch == 0) {
            // two-pass for first chunk (no valid lagged threshold yet)
            #pragma unroll
            for (int nt = 0; nt < 8; nt++) {
                int c = nt * 8 + 2 * lx;
                float2 e = *(const float2*)(sesq + c);
                m0 = fminf(m0, fminf(__fmaf_rn(acc[nt][0], -2.0f, e.x),
                                     __fmaf_rn(acc[nt][1], -2.0f, e.y)));
                m1 = fminf(m1, fminf(__fmaf_rn(acc[nt][2], -2.0f, e.x),
                                     __fmaf_rn(acc[nt][3], -2.0f, e.y)));
            }
            #pragma unroll
            for (int off = 1; off <= 2; off <<= 1) {
                m0 = fminf(m0, __shfl_xor_sync(0xffffffffu, m0, off));
                m1 = fminf(m1, __shfl_xor_sync(0xffffffffu, m1, off));
            }
            rmin0 = m0; thr0 = rmin0 + EPSF;
            rmin1 = m1; thr1 = rmin1 + EPSF;
            #pragma unroll
            for (int nt = 0; nt < 8; nt++) {
                int c = nt * 8 + 2 * lx;
                float2 e = *(const float2*)(sesq + c);
                float s0 = __fmaf_rn(acc[nt][0], -2.0f, e.x);
                float s1 = __fmaf_rn(acc[nt][1], -2.0f, e.y);
                float s2 = __fmaf_rn(acc[nt][2], -2.0f, e.x);
                float s3 = __fmaf_rn(acc[nt][3], -2.0f, e.y);
                if (s0 <= thr0) PUSH(row0, c);
                if (s1 <= thr0) PUSH(row0, c + 1);
                if (s2 <= thr1) PUSH(row0 + 8, c);
                if (s3 <= thr1) PUSH(row0 + 8, c + 1);
            }
        } else {
            // single fused pass with lagged threshold (safe: 2*err << EPSF)
            #pragma unroll
            for (int nt = 0; nt < 8; nt++) {
                int c = ch * 64 + nt * 8 + 2 * lx;
                float2 e = *(const float2*)(sesq + c);
                float s0 = __fmaf_rn(acc[nt][0], -2.0f, e.x);
                float s1 = __fmaf_rn(acc[nt][1], -2.0f, e.y);
                float s2 = __fmaf_rn(acc[nt][2], -2.0f, e.x);
                float s3 = __fmaf_rn(acc[nt][3], -2.0f, e.y);
                if (s0 <= thr0) PUSH(row0, c);
                if (s1 <= thr0) PUSH(row0, c + 1);
                if (s2 <= thr1) PUSH(row0 + 8, c);
                if (s3 <= thr1) PUSH(row0 + 8, c + 1);
                m0 = fminf(m0, fminf(s0, s1));
                m1 = fminf(m1, fminf(s2, s3));
            }
            #pragma unroll
            for (int off = 1; off <= 2; off <<= 1) {
                m0 = fminf(m0, __shfl_xor_sync(0xffffffffu, m0, off));
                m1 = fminf(m1, __shfl_xor_sync(0xffffffffu, m1, off));
            }
            rmin0 = fminf(rmin0, m0); thr0 = rmin0 + EPSF;
            rmin1 = fminf(rmin1, m1); thr1 = rmin1 + EPSF;
        }
    }
    __syncthreads();

    // ---- exact rescore (reference-identical fp32 chains); 2 threads per row ----
    {
        int row = (tid < 128) ? tid : tid - 128;
        int start = (tid < 128) ? 0 : 1;
        int cnt = scnt[row];
        const float* zr = szt + row * 73;
        float zsqv = szsq[row];
        const float* cbm = cbk + (size_t)m * N_E * E_DIM;
        float bd = INFF; int bi = 0x7fffffff;

        auto exact_d = [&](int c) -> float {
            const float* cr = cbm + (size_t)c * E_DIM;
            float s = 0.0f;
            #pragma unroll
            for (int g4 = 0; g4 < 4; g4++) {
                float4 c0 = *(const float4*)(cr + g4 * 16);
                float4 c1 = *(const float4*)(cr + g4 * 16 + 4);
                float4 c2 = *(const float4*)(cr + g4 * 16 + 8);
                float4 c3 = *(const float4*)(cr + g4 * 16 + 12);
                const float* zp = zr + g4 * 16;
                s = __fmaf_rn(zp[0],  c0.x, s); s = __fmaf_rn(zp[1],  c0.y, s);
                s = __fmaf_rn(zp[2],  c0.z, s); s = __fmaf_rn(zp[3],  c0.w, s);
                s = __fmaf_rn(zp[4],  c1.x, s); s = __fmaf_rn(zp[5],  c1.y, s);
                s = __fmaf_rn(zp[6],  c1.z, s); s = __fmaf_rn(zp[7],  c1.w, s);
                s = __fmaf_rn(zp[8],  c2.x, s); s = __fmaf_rn(zp[9],  c2.y, s);
                s = __fmaf_rn(zp[10], c2.z, s); s = __fmaf_rn(zp[11], c2.w, s);
                s = __fmaf_rn(zp[12], c3.x, s); s = __fmaf_rn(zp[13], c3.y, s);
                s = __fmaf_rn(zp[14], c3.z, s); s = __fmaf_rn(zp[15], c3.w, s);
            }
            return __fsub_rn(__fadd_rn(zsqv, sesq[c]), __fmul_rn(2.0f, s));
        };

        if (cnt <= CAP) {
            for (int i = start; i < cnt; i += 2) {
                int c = scand[row * CAP + i];
                float d = exact_d(c);
                if (d < bd || (d == bd && c < bi)) { bd = d; bi = c; }
            }
        } else {  // overflow fallback: full exact scan (provably correct, ~never)
            for (int c = start; c < N_E; c += 2) {
                float d = exact_d(c);
                if (d < bd || (d == bd && c < bi)) { bd = d; bi = c; }
            }
        }
        rbd[tid] = bd; rbi[tid] = bi;
    }
    __syncthreads();
    if (tid < 128) {
        float bd = rbd[tid]; int bi = rbi[tid];
        float d2 = rbd[tid + 128]; int i2 = rbi[tid + 128];
        if (d2 < bd || (d2 == bd && i2 < bi)) { bd = d2; bi = i2; }
        swin[tid] = bi;
        outIdx[m * NPOS + n0 + tid] = (float)bi;
        atomicAdd(outBins + bi, 1.0f);   // integer-valued float adds: exact
    }
    __syncthreads();

    // ---- gather winning code rows into sq[row][d], stride 65 (overlay) ----
    float* sq = sm + S_SQ;
    const float* cbm = cbk + (size_t)m * N_E * E_DIM;
    #pragma unroll
    for (int it = 0; it < 8; it++) {
        int i = tid + it * 256;
        int row = i >> 4, d4 = (i & 15) * 4;
        int idx = swin[row];
        float4 v = *(const float4*)(cbm + (size_t)idx * E_DIM + d4);
        float* dp = sq + row * 65 + d4;
        dp[0] = v.x; dp[1] = v.y; dp[2] = v.z; dp[3] = v.w;
    }
    __syncthreads();

    // ---- z_vq = zf + (zq - zf); loss partial in double ----
    double lsum = 0.0;
    float* ob = outZvq + ((size_t)(b * CC_ + m * E_DIM)) * HW_ + p0;
    #pragma unroll
    for (int it = 0; it < 8; it++) {
        int i = tid + it * 256;
        int d = i >> 5, j4 = (i & 31) * 4;
        float o[4];
        #pragma unroll
        for (int q = 0; q < 4; q++) {
            float zf = szt[(j4 + q) * 73 + d];
            float zq = sq[(j4 + q) * 65 + d];
            float df = __fsub_rn(zq, zf);
            o[q] = __fadd_rn(zf, df);
            lsum += (double)df * (double)df;
        }
        *(float4*)(ob + (size_t)d * HW_ + j4) = make_float4(o[0], o[1], o[2], o[3]);
    }

    #pragma unroll
    for (int off = 16; off > 0; off >>= 1)
        lsum += __shfl_down_sync(0xffffffffu, lsum, off);
    if (lane == 0) swarp[wid] = lsum;
    __syncthreads();
    if (wid == 0) {
        double v = (lane < 8) ? swarp[lane] : 0.0;
        #pragma unroll
        for (int off = 4; off > 0; off >>= 1)
            v += __shfl_down_sync(0xffffffffu, v, off);
        if (lane == 0) g_part[m * 128 + blockIdx.x] = v;
    }
}

// ---------------- K3: finalize loss ---------------------------------------------
__global__ void pq_loss_kernel(float* __restrict__ outLoss) {
    __shared__ double sred[256];
    int t = threadIdx.x;
    double s = 0.0;
    for (int i = t; i < 1024; i += 256) s += g_part[i];
    sred[t] = s;
    __syncthreads();
    for (int off = 128; off > 0; off >>= 1) {
        if (t < off) sred[t] += sred[t + off];
        __syncthreads();
    }
    if (t == 0) {
        double loss = 1.25 * sred[0] / (double)((size_t)NPOS * E_DIM);
        outLoss[0] = (float)loss;
    }
}

// ---------------- launch ----------------------------------------------------------
extern "C" void kernel_launch(void* const* d_in, const int* in_sizes, int n_in,
                              void* d_out, int out_size)
{
    const float* z   = (const float*)d_in[0];
    const float* cbk = (const float*)d_in[1];
    if (n_in >= 2 && in_sizes[0] == M_SUB * N_E * E_DIM) {  // swapped-order safety
        z   = (const float*)d_in[1];
        cbk = (const float*)d_in[0];
    }
    float* out = (float*)d_out;
    float* outZvq  = out + OFF_ZVQ;
    float* outLoss = out + OFF_LOSS;
    float* outIdx  = out + OFF_IDX;
    float* outBins = out + OFF_BIN;

    const int dyn_smem = S_TOT * 4;   // 80384 B
    cudaFuncSetAttribute(pq_dist_kernel,
                         cudaFuncAttributeMaxDynamicSharedMemorySize, dyn_smem);

    pq_init_kernel<<<1, 1024>>>(outBins);
    pq_esq_kernel<<<(M_SUB * N_E + 255) / 256, 256>>>(cbk);
    pq_tr_kernel<<<64, 256>>>(cbk);
    dim3 g1(NPOS / 128, M_SUB);
    pq_dist_kernel<<<g1, 256, dyn_smem>>>(z, cbk, outZvq, outIdx, outBins);
    pq_loss_kernel<<<1, 256>>>(outLoss);
}

// round 14
// speedup vs baseline: 2.9637x; 1.9327x over previous
#include <cuda_runtime.h>
#include <cstdint>

// Problem constants
#define M_SUB   8
#define N_E     1024
#define E_DIM   64
#define BS_     16
#define CC_     512
#define HW_     1024
#define NPOS    16384            // BS_*HW_

// Output layout (float32)
#define OFF_ZVQ  0
#define OFF_LOSS 8388608
#define OFF_IDX  8388609
#define OFF_BIN  8519681

#define CAP   32        // candidate cap per row
#define EPSF  2e-3f     // collect threshold (>= 3x worst-case tf32 error bound)

// Scratch (device globals; no allocation allowed)
__device__ float  g_esq[M_SUB * N_E];
__device__ float  g_cbt[M_SUB * E_DIM * N_E];   // transposed codebooks [m][k][code]
__device__ double g_part[1024];

// ---------------- helpers ------------------------------------------------------
__device__ __forceinline__ unsigned fkey(float f) {          // order-preserving uint
    unsigned u = __float_as_uint(f);
    return (u & 0x80000000u) ? ~u : (u | 0x80000000u);
}
__device__ __forceinline__ float funkey(unsigned k) {
    return __uint_as_float((k & 0x80000000u) ? (k & 0x7fffffffu) : ~k);
}

__device__ __forceinline__ void mma_tf32(float& d0, float& d1, float& d2, float& d3,
                                         unsigned a0, unsigned a1, unsigned a2, unsigned a3,
                                         unsigned b0, unsigned b1) {
    asm volatile("mma.sync.aligned.m16n8k8.row.col.f32.tf32.tf32.f32 "
                 "{%0,%1,%2,%3}, {%4,%5,%6,%7}, {%8,%9}, {%0,%1,%2,%3};"
                 : "+f"(d0), "+f"(d1), "+f"(d2), "+f"(d3)
                 : "r"(a0), "r"(a1), "r"(a2), "r"(a3), "r"(b0), "r"(b1));
}

// ---------------- K0: zero bins -------------------------------------------------
__global__ void pq_init_kernel(float* __restrict__ outBins) {
    int t = threadIdx.x;
    if (t < N_E) outBins[t] = 0.0f;
}

// ---------------- K_esq: per-code squared norms (mul then sequential add) -------
__global__ void pq_esq_kernel(const float* __restrict__ cbk) {
    int t = blockIdx.x * blockDim.x + threadIdx.x;
    if (t >= M_SUB * N_E) return;
    const float* p = cbk + (size_t)t * E_DIM;
    float s = 0.0f;
    #pragma unroll
    for (int d = 0; d < E_DIM; d++) {
        float v = p[d];
        s = __fadd_rn(s, __fmul_rn(v, v));
    }
    g_esq[t] = s;
}

// ---------------- K_tr: transpose codebooks to k-major --------------------------
__global__ void pq_tr_kernel(const float* __restrict__ cbk) {
    __shared__ float st[64 * 128];
    int m  = blockIdx.x >> 3;
    int ct = (blockIdx.x & 7) * 128;
    int tid = threadIdx.x;
    int code = tid >> 1;
    int kh = (tid & 1) * 32;
    const float* src = cbk + ((size_t)(m * N_E) + ct + code) * E_DIM + kh;
    #pragma unroll
    for (int q = 0; q < 8; q++) {
        float4 v = *(const float4*)(src + q * 4);
        st[(kh + q * 4 + 0) * 128 + code] = v.x;
        st[(kh + q * 4 + 1) * 128 + code] = v.y;
        st[(kh + q * 4 + 2) * 128 + code] = v.z;
        st[(kh + q * 4 + 3) * 128 + code] = v.w;
    }
    __syncthreads();
    float* dst = g_cbt + (size_t)m * E_DIM * N_E + ct;
    #pragma unroll
    for (int it = 0; it < 8; it++) {
        int i = tid + it * 256;
        int k = i >> 5, c4 = (i & 31) * 4;
        *(float4*)(dst + (size_t)k * N_E + c4) = *(const float4*)(st + k * 128 + c4);
    }
}

// ---------------- K1: tf32 MMA scoring + exact rescore + fused epilogue ---------
// Block 256 threads (8 warps). Tile: 128 rows x 1024 codes. grid = (128, 8).
// smem carve (floats):
#define S_ZT    0            // z tile [128][73]           (9344)
#define S_CB    9344         // codebook chunk [64][72]    (4608)
#define S_CAND  13952        // candidates [128][CAP] int  (4096)
#define S_ESQ   18048        // esq                        (1024)
#define S_ZSQ   19072        // zsq                        (128)
#define S_CNT   19200        // counters int               (128)
#define S_RMIN  19328        // row min keys uint          (128)
#define S_WIN   19456        // winners int                (128)
#define S_RBD   19584        // rescore partial d          (256)
#define S_RBI   19840        // rescore partial idx int    (256)
#define S_TOT   20096        // 80384 bytes
#define S_SQ    9344         // gather overlay (needs 8320 <= 4608+4096)

__global__ void __launch_bounds__(256, 2)
pq_dist_kernel(const float* __restrict__ z,
               const float* __restrict__ cbk,
               float* __restrict__ outZvq,
               float* __restrict__ outIdx,
               float* __restrict__ outBins)
{
    extern __shared__ float sm[];
    float*    szt  = sm + S_ZT;
    float*    scb  = sm + S_CB;
    int*      scand= (int*)(sm + S_CAND);
    float*    sesq = sm + S_ESQ;
    float*    szsq = sm + S_ZSQ;
    int*      scnt = (int*)(sm + S_CNT);
    unsigned* srmin= (unsigned*)(sm + S_RMIN);
    int*      swin = (int*)(sm + S_WIN);
    float*    rbd  = sm + S_RBD;
    int*      rbi  = (int*)(sm + S_RBI);
    __shared__ double swarp[8];

    const int m  = blockIdx.y;
    const int n0 = blockIdx.x * 128;
    const int b  = n0 >> 10;
    const int p0 = n0 & 1023;
    const int tid  = threadIdx.x;
    const int wid  = tid >> 5;
    const int lane = tid & 31;
    const int gg   = lane >> 2;      // group id 0..7
    const int lx   = lane & 3;       // thread-in-group
    const int row0 = wid * 16 + gg;  // rows owned by this thread's D frags
    const float INFF = __int_as_float(0x7f800000);

    // ---- load z tile [pos][d] (transpose from gmem [d][pos]) ----
    const float* zbase = z + ((size_t)(b * CC_ + m * E_DIM) * HW_) + p0;
    #pragma unroll
    for (int it = 0; it < 8; it++) {
        int i = tid + it * 256;
        int d = i >> 5, j4 = (i & 31) * 4;
        float4 v = *(const float4*)(zbase + (size_t)d * HW_ + j4);
        szt[(j4 + 0) * 73 + d] = v.x;
        szt[(j4 + 1) * 73 + d] = v.y;
        szt[(j4 + 2) * 73 + d] = v.z;
        szt[(j4 + 3) * 73 + d] = v.w;
    }
    #pragma unroll
    for (int it = 0; it < 4; it++)
        sesq[tid + it * 256] = g_esq[m * N_E + tid + it * 256];
    if (tid < 128) { scnt[tid] = 0; srmin[tid] = 0xffffffffu; }
    __syncthreads();

    // ---- per-row ||z||^2 (sequential chain, matches reference) ----
    if (tid < 128) {
        float s = 0.0f;
        const float* zr = szt + tid * 73;
        #pragma unroll
        for (int k = 0; k < E_DIM; k++)
            s = __fadd_rn(s, __fmul_rn(zr[k], zr[k]));
        szsq[tid] = s;
    }

    // ---- A fragments (held in regs for whole kernel): rows row0/row0+8, k=64 ----
    unsigned afr[8][4];
    {
        const float* za = szt + row0 * 73 + lx;
        const float* zb = szt + (row0 + 8) * 73 + lx;
        #pragma unroll
        for (int ks = 0; ks < 8; ks++) {
            afr[ks][0] = __float_as_uint(za[8 * ks]);
            afr[ks][1] = __float_as_uint(zb[8 * ks]);
            afr[ks][2] = __float_as_uint(za[8 * ks + 4]);
            afr[ks][3] = __float_as_uint(zb[8 * ks + 4]);
        }
    }

    // ---- 16 chunks of 64 codes: MMA -> scores -> running min -> collect ----
    const float* ctb = g_cbt + (size_t)m * (E_DIM * N_E);
    for (int ch = 0; ch < 16; ch++) {
        __syncthreads();   // prev chunk fully consumed
        #pragma unroll
        for (int it = 0; it < 4; it++) {
            int i = tid + it * 256;
            int k = i >> 4, n4 = (i & 15) * 4;
            float4 v = *(const float4*)(ctb + (size_t)k * N_E + ch * 64 + n4);
            *(float4*)(scb + k * 72 + n4) = v;
        }
        __syncthreads();   // chunk ready

        float acc[8][4];
        #pragma unroll
        for (int nt = 0; nt < 8; nt++)
            #pragma unroll
            for (int q = 0; q < 4; q++) acc[nt][q] = 0.0f;

        const float* bp = scb + lx * 72 + gg;
        #pragma unroll
        for (int ks = 0; ks < 8; ks++) {
            #pragma unroll
            for (int nt = 0; nt < 8; nt++) {
                unsigned b0 = __float_as_uint(bp[ks * 576 + nt * 8]);
                unsigned b1 = __float_as_uint(bp[ks * 576 + 288 + nt * 8]);
                mma_tf32(acc[nt][0], acc[nt][1], acc[nt][2], acc[nt][3],
                         afr[ks][0], afr[ks][1], afr[ks][2], afr[ks][3], b0, b1);
            }
        }

        // pass 1: scores esq[c] - 2*dot, cached IN PLACE into acc; running min
        float m0 = INFF, m1 = INFF;
        #pragma unroll
        for (int nt = 0; nt < 8; nt++) {
            int c = ch * 64 + nt * 8 + 2 * lx;
            float2 e = *(const float2*)(sesq + c);
            float s0 = __fmaf_rn(acc[nt][0], -2.0f, e.x);
            float s1 = __fmaf_rn(acc[nt][1], -2.0f, e.y);
            float s2 = __fmaf_rn(acc[nt][2], -2.0f, e.x);
            float s3 = __fmaf_rn(acc[nt][3], -2.0f, e.y);
            acc[nt][0] = s0; acc[nt][1] = s1; acc[nt][2] = s2; acc[nt][3] = s3;
            m0 = fminf(m0, fminf(s0, s1));
            m1 = fminf(m1, fminf(s2, s3));
        }
        #pragma unroll
        for (int off = 1; off <= 2; off <<= 1) {
            m0 = fminf(m0, __shfl_xor_sync(0xffffffffu, m0, off));
            m1 = fminf(m1, __shfl_xor_sync(0xffffffffu, m1, off));
        }
        if (lx == 0) {
            atomicMin(srmin + row0, fkey(m0));
            atomicMin(srmin + row0 + 8, fkey(m1));
        }
        __syncthreads();   // row minima include this chunk

        // pass 2: collect (scores read from acc; no recompute, no esq reload)
        float thr0 = funkey(srmin[row0]) + EPSF;
        float thr1 = funkey(srmin[row0 + 8]) + EPSF;
        #pragma unroll
        for (int nt = 0; nt < 8; nt++) {
            int c = ch * 64 + nt * 8 + 2 * lx;
            if (acc[nt][0] <= thr0) { int p = atomicAdd(scnt + row0, 1);     if (p < CAP) scand[row0 * CAP + p] = c; }
            if (acc[nt][1] <= thr0) { int p = atomicAdd(scnt + row0, 1);     if (p < CAP) scand[row0 * CAP + p] = c + 1; }
            if (acc[nt][2] <= thr1) { int p = atomicAdd(scnt + row0 + 8, 1); if (p < CAP) scand[(row0 + 8) * CAP + p] = c; }
            if (acc[nt][3] <= thr1) { int p = atomicAdd(scnt + row0 + 8, 1); if (p < CAP) scand[(row0 + 8) * CAP + p] = c + 1; }
        }
    }
    __syncthreads();

    // ---- exact rescore (reference-identical fp32 chains); 2 threads per row ----
    {
        int row = (tid < 128) ? tid : tid - 128;
        int start = (tid < 128) ? 0 : 1;
        int cnt = scnt[row];
        const float* zr = szt + row * 73;
        float zsqv = szsq[row];
        const float* cbm = cbk + (size_t)m * N_E * E_DIM;
        float bd = INFF; int bi = 0x7fffffff;

        auto exact_d = [&](int c) -> float {
            const float* cr = cbm + (size_t)c * E_DIM;
            float s = 0.0f;
            #pragma unroll
            for (int g4 = 0; g4 < 4; g4++) {
                float4 c0 = *(const float4*)(cr + g4 * 16);
                float4 c1 = *(const float4*)(cr + g4 * 16 + 4);
                float4 c2 = *(const float4*)(cr + g4 * 16 + 8);
                float4 c3 = *(const float4*)(cr + g4 * 16 + 12);
                const float* zp = zr + g4 * 16;
                s = __fmaf_rn(zp[0],  c0.x, s); s = __fmaf_rn(zp[1],  c0.y, s);
                s = __fmaf_rn(zp[2],  c0.z, s); s = __fmaf_rn(zp[3],  c0.w, s);
                s = __fmaf_rn(zp[4],  c1.x, s); s = __fmaf_rn(zp[5],  c1.y, s);
                s = __fmaf_rn(zp[6],  c1.z, s); s = __fmaf_rn(zp[7],  c1.w, s);
                s = __fmaf_rn(zp[8],  c2.x, s); s = __fmaf_rn(zp[9],  c2.y, s);
                s = __fmaf_rn(zp[10], c2.z, s); s = __fmaf_rn(zp[11], c2.w, s);
                s = __fmaf_rn(zp[12], c3.x, s); s = __fmaf_rn(zp[13], c3.y, s);
                s = __fmaf_rn(zp[14], c3.z, s); s = __fmaf_rn(zp[15], c3.w, s);
            }
            return __fsub_rn(__fadd_rn(zsqv, sesq[c]), __fmul_rn(2.0f, s));
        };

        if (cnt <= CAP) {
            for (int i = start; i < cnt; i += 2) {
                int c = scand[row * CAP + i];
                float d = exact_d(c);
                if (d < bd || (d == bd && c < bi)) { bd = d; bi = c; }
            }
        } else {  // overflow fallback: full exact scan (provably correct, ~never)
            for (int c = start; c < N_E; c += 2) {
                float d = exact_d(c);
                if (d < bd || (d == bd && c < bi)) { bd = d; bi = c; }
            }
        }
        rbd[tid] = bd; rbi[tid] = bi;
    }
    __syncthreads();
    if (tid < 128) {
        float bd = rbd[tid]; int bi = rbi[tid];
        float d2 = rbd[tid + 128]; int i2 = rbi[tid + 128];
        if (d2 < bd || (d2 == bd && i2 < bi)) { bd = d2; bi = i2; }
        swin[tid] = bi;
        outIdx[m * NPOS + n0 + tid] = (float)bi;
        atomicAdd(outBins + bi, 1.0f);   // integer-valued float adds: exact
    }
    __syncthreads();

    // ---- gather winning code rows into sq[row][d], stride 65 (overlay) ----
    float* sq = sm + S_SQ;
    const float* cbm = cbk + (size_t)m * N_E * E_DIM;
    #pragma unroll
    for (int it = 0; it < 8; it++) {
        int i = tid + it * 256;
        int row = i >> 4, d4 = (i & 15) * 4;
        int idx = swin[row];
        float4 v = *(const float4*)(cbm + (size_t)idx * E_DIM + d4);
        float* dp = sq + row * 65 + d4;
        dp[0] = v.x; dp[1] = v.y; dp[2] = v.z; dp[3] = v.w;
    }
    __syncthreads();

    // ---- z_vq = zf + (zq - zf); loss partial in double ----
    double lsum = 0.0;
    float* ob = outZvq + ((size_t)(b * CC_ + m * E_DIM)) * HW_ + p0;
    #pragma unroll
    for (int it = 0; it < 8; it++) {
        int i = tid + it * 256;
        int d = i >> 5, j4 = (i & 31) * 4;
        float o[4];
        #pragma unroll
        for (int q = 0; q < 4; q++) {
            float zf = szt[(j4 + q) * 73 + d];
            float zq = sq[(j4 + q) * 65 + d];
            float df = __fsub_rn(zq, zf);
            o[q] = __fadd_rn(zf, df);
            lsum += (double)df * (double)df;
        }
        *(float4*)(ob + (size_t)d * HW_ + j4) = make_float4(o[0], o[1], o[2], o[3]);
    }

    #pragma unroll
    for (int off = 16; off > 0; off >>= 1)
        lsum += __shfl_down_sync(0xffffffffu, lsum, off);
    if (lane == 0) swarp[wid] = lsum;
    __syncthreads();
    if (wid == 0) {
        double v = (lane < 8) ? swarp[lane] : 0.0;
        #pragma unroll
        for (int off = 4; off > 0; off >>= 1)
            v += __shfl_down_sync(0xffffffffu, v, off);
        if (lane == 0) g_part[m * 128 + blockIdx.x] = v;
    }
}

// ---------------- K3: finalize loss ---------------------------------------------
__global__ void pq_loss_kernel(float* __restrict__ outLoss) {
    __shared__ double sred[256];
    int t = threadIdx.x;
    double s = 0.0;
    for (int i = t; i < 1024; i += 256) s += g_part[i];
    sred[t] = s;
    __syncthreads();
    for (int off = 128; off > 0; off >>= 1) {
        if (t < off) sred[t] += sred[t + off];
        __syncthreads();
    }
    if (t == 0) {
        double loss = 1.25 * sred[0] / (double)((size_t)NPOS * E_DIM);
        outLoss[0] = (float)loss;
    }
}

// ---------------- launch ----------------------------------------------------------
extern "C" void kernel_launch(void* const* d_in, const int* in_sizes, int n_in,
                              void* d_out, int out_size)
{
    const float* z   = (const float*)d_in[0];
    const float* cbk = (const float*)d_in[1];
    if (n_in >= 2 && in_sizes[0] == M_SUB * N_E * E_DIM) {  // swapped-order safety
        z   = (const float*)d_in[1];
        cbk = (const float*)d_in[0];
    }
    float* out = (float*)d_out;
    float* outZvq  = out + OFF_ZVQ;
    float* outLoss = out + OFF_LOSS;
    float* outIdx  = out + OFF_IDX;
    float* outBins = out + OFF_BIN;

    const int dyn_smem = S_TOT * 4;   // 80384 B
    cudaFuncSetAttribute(pq_dist_kernel,
                         cudaFuncAttributeMaxDynamicSharedMemorySize, dyn_smem);

    pq_init_kernel<<<1, 1024>>>(outBins);
    pq_esq_kernel<<<(M_SUB * N_E + 255) / 256, 256>>>(cbk);
    pq_tr_kernel<<<64, 256>>>(cbk);
    dim3 g1(NPOS / 128, M_SUB);
    pq_dist_kernel<<<g1, 256, dyn_smem>>>(z, cbk, outZvq, outIdx, outBins);
    pq_loss_kernel<<<1, 256>>>(outLoss);
}

// round 15
// speedup vs baseline: 3.1110x; 1.0497x over previous
#include <cuda_runtime.h>
#include <cstdint>

// Problem constants
#define M_SUB   8
#define N_E     1024
#define E_DIM   64
#define BS_     16
#define CC_     512
#define HW_     1024
#define NPOS    16384            // BS_*HW_

// Output layout (float32)
#define OFF_ZVQ  0
#define OFF_LOSS 8388608
#define OFF_IDX  8388609
#define OFF_BIN  8519681

#define CAP   32        // candidate cap per row
#define EPSF  2e-3f     // collect threshold (>= 3x worst-case tf32 error bound)

// Scratch (device globals; no allocation allowed)
__device__ float  g_esq[M_SUB * N_E];
__device__ float  g_cbt[M_SUB * E_DIM * N_E];   // transposed codebooks [m][k][code]
__device__ double g_part[1024];

// ---------------- helpers ------------------------------------------------------
__device__ __forceinline__ void mma_tf32(float& d0, float& d1, float& d2, float& d3,
                                         unsigned a0, unsigned a1, unsigned a2, unsigned a3,
                                         unsigned b0, unsigned b1) {
    asm volatile("mma.sync.aligned.m16n8k8.row.col.f32.tf32.tf32.f32 "
                 "{%0,%1,%2,%3}, {%4,%5,%6,%7}, {%8,%9}, {%0,%1,%2,%3};"
                 : "+f"(d0), "+f"(d1), "+f"(d2), "+f"(d3)
                 : "r"(a0), "r"(a1), "r"(a2), "r"(a3), "r"(b0), "r"(b1));
}

// ---------------- K0: zero bins -------------------------------------------------
__global__ void pq_init_kernel(float* __restrict__ outBins) {
    int t = threadIdx.x;
    if (t < N_E) outBins[t] = 0.0f;
}

// ---------------- K_esq: per-code squared norms (mul then sequential add) -------
__global__ void pq_esq_kernel(const float* __restrict__ cbk) {
    int t = blockIdx.x * blockDim.x + threadIdx.x;
    if (t >= M_SUB * N_E) return;
    const float* p = cbk + (size_t)t * E_DIM;
    float s = 0.0f;
    #pragma unroll
    for (int d = 0; d < E_DIM; d++) {
        float v = p[d];
        s = __fadd_rn(s, __fmul_rn(v, v));
    }
    g_esq[t] = s;
}

// ---------------- K_tr: transpose codebooks to k-major --------------------------
__global__ void pq_tr_kernel(const float* __restrict__ cbk) {
    __shared__ float st[64 * 128];
    int m  = blockIdx.x >> 3;
    int ct = (blockIdx.x & 7) * 128;
    int tid = threadIdx.x;
    int code = tid >> 1;
    int kh = (tid & 1) * 32;
    const float* src = cbk + ((size_t)(m * N_E) + ct + code) * E_DIM + kh;
    #pragma unroll
    for (int q = 0; q < 8; q++) {
        float4 v = *(const float4*)(src + q * 4);
        st[(kh + q * 4 + 0) * 128 + code] = v.x;
        st[(kh + q * 4 + 1) * 128 + code] = v.y;
        st[(kh + q * 4 + 2) * 128 + code] = v.z;
        st[(kh + q * 4 + 3) * 128 + code] = v.w;
    }
    __syncthreads();
    float* dst = g_cbt + (size_t)m * E_DIM * N_E + ct;
    #pragma unroll
    for (int it = 0; it < 8; it++) {
        int i = tid + it * 256;
        int k = i >> 5, c4 = (i & 31) * 4;
        *(float4*)(dst + (size_t)k * N_E + c4) = *(const float4*)(st + k * 128 + c4);
    }
}

// ---------------- K1: tf32 MMA scoring + exact rescore + fused epilogue ---------
// Block 256 threads (8 warps). Tile: 128 rows x 1024 codes. grid = (128, 8).
// 8 fill phases of 128 codes; each phase runs two 64-code mma/score halves.
// smem carve (floats):
#define S_ZT    0            // z tile [128][73]           (9344)
#define S_CB    9344         // codebook phase [64][136]   (8704)
#define S_CAND  18048        // candidates [128][CAP] int  (4096)
#define S_ESQ   22144        // esq                        (1024)
#define S_ZSQ   23168        // zsq                        (128)
#define S_CNT   23296        // counters int               (128)
#define S_WIN   23424        // winners int                (128)
#define S_RBD   23552        // rescore partial d          (256)
#define S_RBI   23808        // rescore partial idx int    (256)
#define S_TOT   24064        // 96256 bytes
#define S_SQ    9344         // gather overlay (needs 8320 <= 8704)

__global__ void __launch_bounds__(256, 2)
pq_dist_kernel(const float* __restrict__ z,
               const float* __restrict__ cbk,
               float* __restrict__ outZvq,
               float* __restrict__ outIdx,
               float* __restrict__ outBins)
{
    extern __shared__ float sm[];
    float*    szt  = sm + S_ZT;
    float*    scb  = sm + S_CB;
    int*      scand= (int*)(sm + S_CAND);
    float*    sesq = sm + S_ESQ;
    float*    szsq = sm + S_ZSQ;
    int*      scnt = (int*)(sm + S_CNT);
    int*      swin = (int*)(sm + S_WIN);
    float*    rbd  = sm + S_RBD;
    int*      rbi  = (int*)(sm + S_RBI);
    __shared__ double swarp[8];

    const int m  = blockIdx.y;
    const int n0 = blockIdx.x * 128;
    const int b  = n0 >> 10;
    const int p0 = n0 & 1023;
    const int tid  = threadIdx.x;
    const int wid  = tid >> 5;
    const int lane = tid & 31;
    const int gg   = lane >> 2;      // group id 0..7
    const int lx   = lane & 3;       // thread-in-group
    const int row0 = wid * 16 + gg;  // rows owned by this thread's D frags (warp-excl.)
    const float INFF = __int_as_float(0x7f800000);

    // ---- load z tile [pos][d] (transpose from gmem [d][pos]) ----
    const float* zbase = z + ((size_t)(b * CC_ + m * E_DIM) * HW_) + p0;
    #pragma unroll
    for (int it = 0; it < 8; it++) {
        int i = tid + it * 256;
        int d = i >> 5, j4 = (i & 31) * 4;
        float4 v = *(const float4*)(zbase + (size_t)d * HW_ + j4);
        szt[(j4 + 0) * 73 + d] = v.x;
        szt[(j4 + 1) * 73 + d] = v.y;
        szt[(j4 + 2) * 73 + d] = v.z;
        szt[(j4 + 3) * 73 + d] = v.w;
    }
    #pragma unroll
    for (int it = 0; it < 4; it++)
        sesq[tid + it * 256] = g_esq[m * N_E + tid + it * 256];
    if (tid < 128) scnt[tid] = 0;
    __syncthreads();

    // ---- per-row ||z||^2 (sequential chain, matches reference) ----
    if (tid < 128) {
        float s = 0.0f;
        const float* zr = szt + tid * 73;
        #pragma unroll
        for (int k = 0; k < E_DIM; k++)
            s = __fadd_rn(s, __fmul_rn(zr[k], zr[k]));
        szsq[tid] = s;
    }

    // ---- A fragments (held in regs for whole kernel): rows row0/row0+8, k=64 ----
    unsigned afr[8][4];
    {
        const float* za = szt + row0 * 73 + lx;
        const float* zb = szt + (row0 + 8) * 73 + lx;
        #pragma unroll
        for (int ks = 0; ks < 8; ks++) {
            afr[ks][0] = __float_as_uint(za[8 * ks]);
            afr[ks][1] = __float_as_uint(zb[8 * ks]);
            afr[ks][2] = __float_as_uint(za[8 * ks + 4]);
            afr[ks][3] = __float_as_uint(zb[8 * ks + 4]);
        }
    }

    // ---- 8 phases of 128 codes; two 64-code halves per phase --------------------
    const float* ctb = g_cbt + (size_t)m * (E_DIM * N_E);
    float rmin0 = INFF, rmin1 = INFF;       // register prefix minima (rows warp-excl.)
    for (int ph = 0; ph < 8; ph++) {
        __syncthreads();   // prev phase fully consumed
        // fill 128 codes, k-major [64][136]
        #pragma unroll
        for (int it = 0; it < 8; it++) {
            int i = tid + it * 256;          // 0..2047 float4 slots
            int k = i >> 5, n4 = (i & 31) * 4;
            float4 v = *(const float4*)(ctb + (size_t)k * N_E + ph * 128 + n4);
            *(float4*)(scb + k * 136 + n4) = v;
        }
        __syncthreads();   // phase ready

        #pragma unroll
        for (int h = 0; h < 2; h++) {
            float acc[8][4];
            #pragma unroll
            for (int nt = 0; nt < 8; nt++)
                #pragma unroll
                for (int q = 0; q < 4; q++) acc[nt][q] = 0.0f;

            const float* bp = scb + lx * 136 + gg + h * 64;
            #pragma unroll
            for (int ks = 0; ks < 8; ks++) {
                #pragma unroll
                for (int nt = 0; nt < 8; nt++) {
                    unsigned b0 = __float_as_uint(bp[ks * 1088 + nt * 8]);
                    unsigned b1 = __float_as_uint(bp[ks * 1088 + 544 + nt * 8]);
                    mma_tf32(acc[nt][0], acc[nt][1], acc[nt][2], acc[nt][3],
                             afr[ks][0], afr[ks][1], afr[ks][2], afr[ks][3], b0, b1);
                }
            }

            // pass 1: scores esq[c] - 2*dot, cached IN PLACE into acc; chunk min
            const int cbase = ph * 128 + h * 64;
            float m0 = INFF, m1 = INFF;
            #pragma unroll
            for (int nt = 0; nt < 8; nt++) {
                int c = cbase + nt * 8 + 2 * lx;
                float2 e = *(const float2*)(sesq + c);
                float s0 = __fmaf_rn(acc[nt][0], -2.0f, e.x);
                float s1 = __fmaf_rn(acc[nt][1], -2.0f, e.y);
                float s2 = __fmaf_rn(acc[nt][2], -2.0f, e.x);
                float s3 = __fmaf_rn(acc[nt][3], -2.0f, e.y);
                acc[nt][0] = s0; acc[nt][1] = s1; acc[nt][2] = s2; acc[nt][3] = s3;
                m0 = fminf(m0, fminf(s0, s1));
                m1 = fminf(m1, fminf(s2, s3));
            }
            #pragma unroll
            for (int off = 1; off <= 2; off <<= 1) {
                m0 = fminf(m0, __shfl_xor_sync(0xffffffffu, m0, off));
                m1 = fminf(m1, __shfl_xor_sync(0xffffffffu, m1, off));
            }
            // rows are warp-exclusive: register prefix-min == R14's smem value
            rmin0 = fminf(rmin0, m0);
            rmin1 = fminf(rmin1, m1);
            float thr0 = rmin0 + EPSF;
            float thr1 = rmin1 + EPSF;

            // pass 2: collect (scores read from acc; thresholds incl. this half)
            #pragma unroll
            for (int nt = 0; nt < 8; nt++) {
                int c = cbase + nt * 8 + 2 * lx;
                if (acc[nt][0] <= thr0) { int p = atomicAdd(scnt + row0, 1);     if (p < CAP) scand[row0 * CAP + p] = c; }
                if (acc[nt][1] <= thr0) { int p = atomicAdd(scnt + row0, 1);     if (p < CAP) scand[row0 * CAP + p] = c + 1; }
                if (acc[nt][2] <= thr1) { int p = atomicAdd(scnt + row0 + 8, 1); if (p < CAP) scand[(row0 + 8) * CAP + p] = c; }
                if (acc[nt][3] <= thr1) { int p = atomicAdd(scnt + row0 + 8, 1); if (p < CAP) scand[(row0 + 8) * CAP + p] = c + 1; }
            }
        }
    }
    __syncthreads();

    // ---- exact rescore (reference-identical fp32 chains); 2 threads per row ----
    {
        int row = (tid < 128) ? tid : tid - 128;
        int start = (tid < 128) ? 0 : 1;
        int cnt = scnt[row];
        const float* zr = szt + row * 73;
        float zsqv = szsq[row];
        const float* cbm = cbk + (size_t)m * N_E * E_DIM;
        float bd = INFF; int bi = 0x7fffffff;

        auto exact_d = [&](int c) -> float {
            const float* cr = cbm + (size_t)c * E_DIM;
            float s = 0.0f;
            #pragma unroll
            for (int g4 = 0; g4 < 4; g4++) {
                float4 c0 = *(const float4*)(cr + g4 * 16);
                float4 c1 = *(const float4*)(cr + g4 * 16 + 4);
                float4 c2 = *(const float4*)(cr + g4 * 16 + 8);
                float4 c3 = *(const float4*)(cr + g4 * 16 + 12);
                const float* zp = zr + g4 * 16;
                s = __fmaf_rn(zp[0],  c0.x, s); s = __fmaf_rn(zp[1],  c0.y, s);
                s = __fmaf_rn(zp[2],  c0.z, s); s = __fmaf_rn(zp[3],  c0.w, s);
                s = __fmaf_rn(zp[4],  c1.x, s); s = __fmaf_rn(zp[5],  c1.y, s);
                s = __fmaf_rn(zp[6],  c1.z, s); s = __fmaf_rn(zp[7],  c1.w, s);
                s = __fmaf_rn(zp[8],  c2.x, s); s = __fmaf_rn(zp[9],  c2.y, s);
                s = __fmaf_rn(zp[10], c2.z, s); s = __fmaf_rn(zp[11], c2.w, s);
                s = __fmaf_rn(zp[12], c3.x, s); s = __fmaf_rn(zp[13], c3.y, s);
                s = __fmaf_rn(zp[14], c3.z, s); s = __fmaf_rn(zp[15], c3.w, s);
            }
            return __fsub_rn(__fadd_rn(zsqv, sesq[c]), __fmul_rn(2.0f, s));
        };

        if (cnt <= CAP) {
            for (int i = start; i < cnt; i += 2) {
                int c = scand[row * CAP + i];
                float d = exact_d(c);
                if (d < bd || (d == bd && c < bi)) { bd = d; bi = c; }
            }
        } else {  // overflow fallback: full exact scan (provably correct, ~never)
            for (int c = start; c < N_E; c += 2) {
                float d = exact_d(c);
                if (d < bd || (d == bd && c < bi)) { bd = d; bi = c; }
            }
        }
        rbd[tid] = bd; rbi[tid] = bi;
    }
    __syncthreads();
    if (tid < 128) {
        float bd = rbd[tid]; int bi = rbi[tid];
        float d2 = rbd[tid + 128]; int i2 = rbi[tid + 128];
        if (d2 < bd || (d2 == bd && i2 < bi)) { bd = d2; bi = i2; }
        swin[tid] = bi;
        outIdx[m * NPOS + n0 + tid] = (float)bi;
        atomicAdd(outBins + bi, 1.0f);   // integer-valued float adds: exact
    }
    __syncthreads();

    // ---- gather winning code rows into sq[row][d], stride 65 (overlay) ----
    float* sq = sm + S_SQ;
    const float* cbm = cbk + (size_t)m * N_E * E_DIM;
    #pragma unroll
    for (int it = 0; it < 8; it++) {
        int i = tid + it * 256;
        int row = i >> 4, d4 = (i & 15) * 4;
        int idx = swin[row];
        float4 v = *(const float4*)(cbm + (size_t)idx * E_DIM + d4);
        float* dp = sq + row * 65 + d4;
        dp[0] = v.x; dp[1] = v.y; dp[2] = v.z; dp[3] = v.w;
    }
    __syncthreads();

    // ---- z_vq = zf + (zq - zf); loss partial in double ----
    double lsum = 0.0;
    float* ob = outZvq + ((size_t)(b * CC_ + m * E_DIM)) * HW_ + p0;
    #pragma unroll
    for (int it = 0; it < 8; it++) {
        int i = tid + it * 256;
        int d = i >> 5, j4 = (i & 31) * 4;
        float o[4];
        #pragma unroll
        for (int q = 0; q < 4; q++) {
            float zf = szt[(j4 + q) * 73 + d];
            float zq = sq[(j4 + q) * 65 + d];
            float df = __fsub_rn(zq, zf);
            o[q] = __fadd_rn(zf, df);
            lsum += (double)df * (double)df;
        }
        *(float4*)(ob + (size_t)d * HW_ + j4) = make_float4(o[0], o[1], o[2], o[3]);
    }

    #pragma unroll
    for (int off = 16; off > 0; off >>= 1)
        lsum += __shfl_down_sync(0xffffffffu, lsum, off);
    if (lane == 0) swarp[wid] = lsum;
    __syncthreads();
    if (wid == 0) {
        double v = (lane < 8) ? swarp[lane] : 0.0;
        #pragma unroll
        for (int off = 4; off > 0; off >>= 1)
            v += __shfl_down_sync(0xffffffffu, v, off);
        if (lane == 0) g_part[m * 128 + blockIdx.x] = v;
    }
}

// ---------------- K3: finalize loss ---------------------------------------------
__global__ void pq_loss_kernel(float* __restrict__ outLoss) {
    __shared__ double sred[256];
    int t = threadIdx.x;
    double s = 0.0;
    for (int i = t; i < 1024; i += 256) s += g_part[i];
    sred[t] = s;
    __syncthreads();
    for (int off = 128; off > 0; off >>= 1) {
        if (t < off) sred[t] += sred[t + off];
        __syncthreads();
    }
    if (t == 0) {
        double loss = 1.25 * sred[0] / (double)((size_t)NPOS * E_DIM);
        outLoss[0] = (float)loss;
    }
}

// ---------------- launch ----------------------------------------------------------
extern "C" void kernel_launch(void* const* d_in, const int* in_sizes, int n_in,
                              void* d_out, int out_size)
{
    const float* z   = (const float*)d_in[0];
    const float* cbk = (const float*)d_in[1];
    if (n_in >= 2 && in_sizes[0] == M_SUB * N_E * E_DIM) {  // swapped-order safety
        z   = (const float*)d_in[1];
        cbk = (const float*)d_in[0];
    }
    float* out = (float*)d_out;
    float* outZvq  = out + OFF_ZVQ;
    float* outLoss = out + OFF_LOSS;
    float* outIdx  = out + OFF_IDX;
    float* outBins = out + OFF_BIN;

    const int dyn_smem = S_TOT * 4;   // 96256 B
    cudaFuncSetAttribute(pq_dist_kernel,
                         cudaFuncAttributeMaxDynamicSharedMemorySize, dyn_smem);

    pq_init_kernel<<<1, 1024>>>(outBins);
    pq_esq_kernel<<<(M_SUB * N_E + 255) / 256, 256>>>(cbk);
    pq_tr_kernel<<<64, 256>>>(cbk);
    dim3 g1(NPOS / 128, M_SUB);
    pq_dist_kernel<<<g1, 256, dyn_smem>>>(z, cbk, outZvq, outIdx, outBins);
    pq_loss_kernel<<<1, 256>>>(outLoss);
}

// round 16
// speedup vs baseline: 3.2412x; 1.0418x over previous
#include <cuda_runtime.h>
#include <cuda_fp16.h>
#include <cstdint>

// Problem constants
#define M_SUB   8
#define N_E     1024
#define E_DIM   64
#define BS_     16
#define CC_     512
#define HW_     1024
#define NPOS    16384            // BS_*HW_

// Output layout (float32)
#define OFF_ZVQ  0
#define OFF_LOSS 8388608
#define OFF_IDX  8388609
#define OFF_BIN  8519681

#define CAP   32        // candidate cap per row
#define EPSF  2e-3f     // collect threshold (>= 14x worst-case fp16 error bound)

// Scratch (device globals; no allocation allowed)
__device__ float  g_esq[M_SUB * N_E];
// fp16 codebooks in m16n8k16 B-fragment order:
// per m, 16 chunks of 64 codes; chunk = uint2 frag[ks(4)][nt(8)][gg(8)][lx(4)]
//   frag = { h2(cb[c][16ks+2lx], cb[c][16ks+2lx+1]),
//            h2(cb[c][16ks+2lx+8], cb[c][16ks+2lx+9]) },  c = nt*8+gg
__device__ uint2  g_cbh[M_SUB * 16 * 1024];
__device__ double g_part[1024];

// ---------------- helpers ------------------------------------------------------
__device__ __forceinline__ unsigned h2u(__half2 h) {
    return *reinterpret_cast<unsigned*>(&h);
}
__device__ __forceinline__ void mma_f16(float* d, const unsigned* a,
                                        unsigned b0, unsigned b1) {
    asm volatile("mma.sync.aligned.m16n8k16.row.col.f32.f16.f16.f32 "
                 "{%0,%1,%2,%3}, {%4,%5,%6,%7}, {%8,%9}, {%0,%1,%2,%3};"
                 : "+f"(d[0]), "+f"(d[1]), "+f"(d[2]), "+f"(d[3])
                 : "r"(a[0]), "r"(a[1]), "r"(a[2]), "r"(a[3]), "r"(b0), "r"(b1));
}

// ---------------- K0: zero bins -------------------------------------------------
__global__ void pq_init_kernel(float* __restrict__ outBins) {
    int t = threadIdx.x;
    if (t < N_E) outBins[t] = 0.0f;
}

// ---------------- K_esq: per-code squared norms (mul then sequential add) -------
__global__ void pq_esq_kernel(const float* __restrict__ cbk) {
    int t = blockIdx.x * blockDim.x + threadIdx.x;
    if (t >= M_SUB * N_E) return;
    const float* p = cbk + (size_t)t * E_DIM;
    float s = 0.0f;
    #pragma unroll
    for (int d = 0; d < E_DIM; d++) {
        float v = p[d];
        s = __fadd_rn(s, __fmul_rn(v, v));
    }
    g_esq[t] = s;
}

// ---------------- K_tr: pack codebooks into fp16 fragment order ------------------
// grid = 128 (m x ch), 256 threads, 4 fragment entries each
__global__ void pq_tr_kernel(const float* __restrict__ cbk) {
    int m  = blockIdx.x >> 4;
    int ch = blockIdx.x & 15;
    int tid = threadIdx.x;
    const float* src = cbk + ((size_t)(m * N_E) + ch * 64) * E_DIM;
    uint2* dst = g_cbh + (size_t)blockIdx.x * 1024;
    #pragma unroll
    for (int it = 0; it < 4; it++) {
        int idx = tid + it * 256;            // 0..1023
        int ks = idx >> 8, nt = (idx >> 5) & 7, gg = (idx >> 2) & 7, lx = idx & 3;
        int c  = nt * 8 + gg;
        int k0 = ks * 16 + 2 * lx;
        const float* r = src + (size_t)c * E_DIM;
        uint2 v;
        v.x = h2u(__floats2half2_rn(r[k0],     r[k0 + 1]));
        v.y = h2u(__floats2half2_rn(r[k0 + 8], r[k0 + 9]));
        dst[idx] = v;
    }
}

// ---------------- K1: fp16 MMA scoring + exact rescore + fused epilogue ---------
// Block 256 threads (8 warps). Tile: 128 rows x 1024 codes. grid = (128, 8).
// 8 fill phases of 128 codes (2 fragment chunks); two 64-code halves per phase.
// smem carve (floats):
#define S_ZT    0            // z tile [128][73]            (9344)
#define S_CB    9344         // fragment phase 2048 uint2   (4096)
#define S_CAND  13440        // candidates [128][CAP] int   (4096)
#define S_ESQ   17536        // esq                         (1024)
#define S_ZSQ   18560        // zsq                         (128)
#define S_CNT   18688        // counters int                (128)
#define S_WIN   18816        // winners int                 (128)
#define S_RBD   18944        // rescore partial d           (256)
#define S_RBI   19200        // rescore partial idx int     (256)
#define S_TOT   19456        // 77824 bytes
#define S_SQ    9344         // gather overlay (8320 <= cb+cand+esq = 9216)

__global__ void __launch_bounds__(256, 2)
pq_dist_kernel(const float* __restrict__ z,
               const float* __restrict__ cbk,
               float* __restrict__ outZvq,
               float* __restrict__ outIdx,
               float* __restrict__ outBins)
{
    extern __shared__ float sm[];
    float*    szt  = sm + S_ZT;
    float*    scb  = sm + S_CB;
    int*      scand= (int*)(sm + S_CAND);
    float*    sesq = sm + S_ESQ;
    float*    szsq = sm + S_ZSQ;
    int*      scnt = (int*)(sm + S_CNT);
    int*      swin = (int*)(sm + S_WIN);
    float*    rbd  = sm + S_RBD;
    int*      rbi  = (int*)(sm + S_RBI);
    __shared__ double swarp[8];

    const int m  = blockIdx.y;
    const int n0 = blockIdx.x * 128;
    const int b  = n0 >> 10;
    const int p0 = n0 & 1023;
    const int tid  = threadIdx.x;
    const int wid  = tid >> 5;
    const int lane = tid & 31;
    const int gg   = lane >> 2;      // group id 0..7
    const int lx   = lane & 3;       // thread-in-group
    const int row0 = wid * 16 + gg;  // rows owned by this thread's D frags (warp-excl.)
    const float INFF = __int_as_float(0x7f800000);

    // ---- load z tile [pos][d] (transpose from gmem [d][pos]) ----
    const float* zbase = z + ((size_t)(b * CC_ + m * E_DIM) * HW_) + p0;
    #pragma unroll
    for (int it = 0; it < 8; it++) {
        int i = tid + it * 256;
        int d = i >> 5, j4 = (i & 31) * 4;
        float4 v = *(const float4*)(zbase + (size_t)d * HW_ + j4);
        szt[(j4 + 0) * 73 + d] = v.x;
        szt[(j4 + 1) * 73 + d] = v.y;
        szt[(j4 + 2) * 73 + d] = v.z;
        szt[(j4 + 3) * 73 + d] = v.w;
    }
    #pragma unroll
    for (int it = 0; it < 4; it++)
        sesq[tid + it * 256] = g_esq[m * N_E + tid + it * 256];
    if (tid < 128) scnt[tid] = 0;
    __syncthreads();

    // ---- per-row ||z||^2 (sequential chain, matches reference) ----
    if (tid < 128) {
        float s = 0.0f;
        const float* zr = szt + tid * 73;
        #pragma unroll
        for (int k = 0; k < E_DIM; k++)
            s = __fadd_rn(s, __fmul_rn(zr[k], zr[k]));
        szsq[tid] = s;
    }

    // ---- A fragments fp16 (held in regs): rows row0/row0+8, k=64 ----
    unsigned afr[4][4];
    {
        const float* zr0 = szt + row0 * 73;
        const float* zr1 = szt + (row0 + 8) * 73;
        #pragma unroll
        for (int ks = 0; ks < 4; ks++) {
            int k0 = 16 * ks + 2 * lx;
            afr[ks][0] = h2u(__floats2half2_rn(zr0[k0],     zr0[k0 + 1]));
            afr[ks][1] = h2u(__floats2half2_rn(zr1[k0],     zr1[k0 + 1]));
            afr[ks][2] = h2u(__floats2half2_rn(zr0[k0 + 8], zr0[k0 + 9]));
            afr[ks][3] = h2u(__floats2half2_rn(zr1[k0 + 8], zr1[k0 + 9]));
        }
    }

    // ---- 8 phases of 128 codes; two 64-code halves per phase --------------------
    const uint2* ctb = g_cbh + (size_t)m * 16384;   // 16 chunks x 1024 uint2
    float rmin0 = INFF, rmin1 = INFF;       // register prefix minima (rows warp-excl.)
    for (int ph = 0; ph < 8; ph++) {
        __syncthreads();   // prev phase fully consumed
        // fill 2 fragment chunks = 2048 uint2 = 16KB (contiguous copy)
        {
            const uint4* g4 = (const uint4*)(ctb + ph * 2048);
            uint4* s4 = (uint4*)scb;
            #pragma unroll
            for (int it = 0; it < 4; it++)
                s4[tid + it * 256] = g4[tid + it * 256];
        }
        __syncthreads();   // phase ready

        #pragma unroll
        for (int h = 0; h < 2; h++) {
            float acc[8][4];
            #pragma unroll
            for (int nt = 0; nt < 8; nt++)
                #pragma unroll
                for (int q = 0; q < 4; q++) acc[nt][q] = 0.0f;

            // conflict-free: per (ks,nt) a warp reads one contiguous 256B span
            const uint2* bp = (const uint2*)scb + h * 1024 + gg * 4 + lx;
            #pragma unroll
            for (int ks = 0; ks < 4; ks++) {
                #pragma unroll
                for (int nt = 0; nt < 8; nt++) {
                    uint2 bb = bp[ks * 256 + nt * 32];
                    mma_f16(acc[nt], afr[ks], bb.x, bb.y);
                }
            }

            // pass 1: scores esq[c] - 2*dot, cached IN PLACE into acc; chunk min
            const int cbase = ph * 128 + h * 64;
            float m0 = INFF, m1 = INFF;
            #pragma unroll
            for (int nt = 0; nt < 8; nt++) {
                int c = cbase + nt * 8 + 2 * lx;
                float2 e = *(const float2*)(sesq + c);
                float s0 = __fmaf_rn(acc[nt][0], -2.0f, e.x);
                float s1 = __fmaf_rn(acc[nt][1], -2.0f, e.y);
                float s2 = __fmaf_rn(acc[nt][2], -2.0f, e.x);
                float s3 = __fmaf_rn(acc[nt][3], -2.0f, e.y);
                acc[nt][0] = s0; acc[nt][1] = s1; acc[nt][2] = s2; acc[nt][3] = s3;
                m0 = fminf(m0, fminf(s0, s1));
                m1 = fminf(m1, fminf(s2, s3));
            }
            #pragma unroll
            for (int off = 1; off <= 2; off <<= 1) {
                m0 = fminf(m0, __shfl_xor_sync(0xffffffffu, m0, off));
                m1 = fminf(m1, __shfl_xor_sync(0xffffffffu, m1, off));
            }
            // rows are warp-exclusive: register prefix-min is the exact row min
            rmin0 = fminf(rmin0, m0);
            rmin1 = fminf(rmin1, m1);
            float thr0 = rmin0 + EPSF;
            float thr1 = rmin1 + EPSF;

            // pass 2: collect (scores read from acc; thresholds incl. this half)
            #pragma unroll
            for (int nt = 0; nt < 8; nt++) {
                int c = cbase + nt * 8 + 2 * lx;
                if (acc[nt][0] <= thr0) { int p = atomicAdd(scnt + row0, 1);     if (p < CAP) scand[row0 * CAP + p] = c; }
                if (acc[nt][1] <= thr0) { int p = atomicAdd(scnt + row0, 1);     if (p < CAP) scand[row0 * CAP + p] = c + 1; }
                if (acc[nt][2] <= thr1) { int p = atomicAdd(scnt + row0 + 8, 1); if (p < CAP) scand[(row0 + 8) * CAP + p] = c; }
                if (acc[nt][3] <= thr1) { int p = atomicAdd(scnt + row0 + 8, 1); if (p < CAP) scand[(row0 + 8) * CAP + p] = c + 1; }
            }
        }
    }
    __syncthreads();

    // ---- exact rescore (reference-identical fp32 chains); 2 threads per row ----
    {
        int row = (tid < 128) ? tid : tid - 128;
        int start = (tid < 128) ? 0 : 1;
        int cnt = scnt[row];
        const float* zr = szt + row * 73;
        float zsqv = szsq[row];
        const float* cbm = cbk + (size_t)m * N_E * E_DIM;
        float bd = INFF; int bi = 0x7fffffff;

        auto exact_d = [&](int c) -> float {
            const float* cr = cbm + (size_t)c * E_DIM;
            float s = 0.0f;
            #pragma unroll
            for (int g4 = 0; g4 < 4; g4++) {
                float4 c0 = *(const float4*)(cr + g4 * 16);
                float4 c1 = *(const float4*)(cr + g4 * 16 + 4);
                float4 c2 = *(const float4*)(cr + g4 * 16 + 8);
                float4 c3 = *(const float4*)(cr + g4 * 16 + 12);
                const float* zp = zr + g4 * 16;
                s = __fmaf_rn(zp[0],  c0.x, s); s = __fmaf_rn(zp[1],  c0.y, s);
                s = __fmaf_rn(zp[2],  c0.z, s); s = __fmaf_rn(zp[3],  c0.w, s);
                s = __fmaf_rn(zp[4],  c1.x, s); s = __fmaf_rn(zp[5],  c1.y, s);
                s = __fmaf_rn(zp[6],  c1.z, s); s = __fmaf_rn(zp[7],  c1.w, s);
                s = __fmaf_rn(zp[8],  c2.x, s); s = __fmaf_rn(zp[9],  c2.y, s);
                s = __fmaf_rn(zp[10], c2.z, s); s = __fmaf_rn(zp[11], c2.w, s);
                s = __fmaf_rn(zp[12], c3.x, s); s = __fmaf_rn(zp[13], c3.y, s);
                s = __fmaf_rn(zp[14], c3.z, s); s = __fmaf_rn(zp[15], c3.w, s);
            }
            return __fsub_rn(__fadd_rn(zsqv, sesq[c]), __fmul_rn(2.0f, s));
        };

        if (cnt <= CAP) {
            for (int i = start; i < cnt; i += 2) {
                int c = scand[row * CAP + i];
                float d = exact_d(c);
                if (d < bd || (d == bd && c < bi)) { bd = d; bi = c; }
            }
        } else {  // overflow fallback: full exact scan (provably correct, ~never)
            for (int c = start; c < N_E; c += 2) {
                float d = exact_d(c);
                if (d < bd || (d == bd && c < bi)) { bd = d; bi = c; }
            }
        }
        rbd[tid] = bd; rbi[tid] = bi;
    }
    __syncthreads();
    if (tid < 128) {
        float bd = rbd[tid]; int bi = rbi[tid];
        float d2 = rbd[tid + 128]; int i2 = rbi[tid + 128];
        if (d2 < bd || (d2 == bd && i2 < bi)) { bd = d2; bi = i2; }
        swin[tid] = bi;
        outIdx[m * NPOS + n0 + tid] = (float)bi;
        atomicAdd(outBins + bi, 1.0f);   // integer-valued float adds: exact
    }
    __syncthreads();

    // ---- gather winning code rows into sq[row][d], stride 65 (overlay) ----
    float* sq = sm + S_SQ;
    const float* cbm = cbk + (size_t)m * N_E * E_DIM;
    #pragma unroll
    for (int it = 0; it < 8; it++) {
        int i = tid + it * 256;
        int row = i >> 4, d4 = (i & 15) * 4;
        int idx = swin[row];
        float4 v = *(const float4*)(cbm + (size_t)idx * E_DIM + d4);
        float* dp = sq + row * 65 + d4;
        dp[0] = v.x; dp[1] = v.y; dp[2] = v.z; dp[3] = v.w;
    }
    __syncthreads();

    // ---- z_vq = zf + (zq - zf); loss partial in double ----
    double lsum = 0.0;
    float* ob = outZvq + ((size_t)(b * CC_ + m * E_DIM)) * HW_ + p0;
    #pragma unroll
    for (int it = 0; it < 8; it++) {
        int i = tid + it * 256;
        int d = i >> 5, j4 = (i & 31) * 4;
        float o[4];
        #pragma unroll
        for (int q = 0; q < 4; q++) {
            float zf = szt[(j4 + q) * 73 + d];
            float zq = sq[(j4 + q) * 65 + d];
            float df = __fsub_rn(zq, zf);
            o[q] = __fadd_rn(zf, df);
            lsum += (double)df * (double)df;
        }
        *(float4*)(ob + (size_t)d * HW_ + j4) = make_float4(o[0], o[1], o[2], o[3]);
    }

    #pragma unroll
    for (int off = 16; off > 0; off >>= 1)
        lsum += __shfl_down_sync(0xffffffffu, lsum, off);
    if (lane == 0) swarp[wid] = lsum;
    __syncthreads();
    if (wid == 0) {
        double v = (lane < 8) ? swarp[lane] : 0.0;
        #pragma unroll
        for (int off = 4; off > 0; off >>= 1)
            v += __shfl_down_sync(0xffffffffu, v, off);
        if (lane == 0) g_part[m * 128 + blockIdx.x] = v;
    }
}

// ---------------- K3: finalize loss ---------------------------------------------
__global__ void pq_loss_kernel(float* __restrict__ outLoss) {
    __shared__ double sred[256];
    int t = threadIdx.x;
    double s = 0.0;
    for (int i = t; i < 1024; i += 256) s += g_part[i];
    sred[t] = s;
    __syncthreads();
    for (int off = 128; off > 0; off >>= 1) {
        if (t < off) sred[t] += sred[t + off];
        __syncthreads();
    }
    if (t == 0) {
        double loss = 1.25 * sred[0] / (double)((size_t)NPOS * E_DIM);
        outLoss[0] = (float)loss;
    }
}

// ---------------- launch ----------------------------------------------------------
extern "C" void kernel_launch(void* const* d_in, const int* in_sizes, int n_in,
                              void* d_out, int out_size)
{
    const float* z   = (const float*)d_in[0];
    const float* cbk = (const float*)d_in[1];
    if (n_in >= 2 && in_sizes[0] == M_SUB * N_E * E_DIM) {  // swapped-order safety
        z   = (const float*)d_in[1];
        cbk = (const float*)d_in[0];
    }
    float* out = (float*)d_out;
    float* outZvq  = out + OFF_ZVQ;
    float* outLoss = out + OFF_LOSS;
    float* outIdx  = out + OFF_IDX;
    float* outBins = out + OFF_BIN;

    const int dyn_smem = S_TOT * 4;   // 77824 B
    cudaFuncSetAttribute(pq_dist_kernel,
                         cudaFuncAttributeMaxDynamicSharedMemorySize, dyn_smem);

    pq_init_kernel<<<1, 1024>>>(outBins);
    pq_esq_kernel<<<(M_SUB * N_E + 255) / 256, 256>>>(cbk);
    pq_tr_kernel<<<128, 256>>>(cbk);
    dim3 g1(NPOS / 128, M_SUB);
    pq_dist_kernel<<<g1, 256, dyn_smem>>>(z, cbk, outZvq, outIdx, outBins);
    pq_loss_kernel<<<1, 256>>>(outLoss);
}

// round 17
// speedup vs baseline: 3.5180x; 1.0854x over previous
#include <cuda_runtime.h>
#include <cuda_fp16.h>
#include <cstdint>

// Problem constants
#define M_SUB   8
#define N_E     1024
#define E_DIM   64
#define BS_     16
#define CC_     512
#define HW_     1024
#define NPOS    16384            // BS_*HW_

// Output layout (float32)
#define OFF_ZVQ  0
#define OFF_LOSS 8388608
#define OFF_IDX  8388609
#define OFF_BIN  8519681

#define CAP   32        // candidate cap per row
#define EPSF  2e-3f     // collect threshold (>= 14x worst-case fp16 error bound)

// Scratch (device globals; no allocation allowed)
__device__ float  g_esq[M_SUB * N_E];
// fp16 codebooks in m16n8k16 B-fragment order:
// per m, 16 chunks of 64 codes; chunk = uint2 frag[ks(4)][nt(8)][gg(8)][lx(4)]
__device__ uint2  g_cbh[M_SUB * 16 * 1024];
__device__ double g_part[1024];

// ---------------- helpers ------------------------------------------------------
__device__ __forceinline__ unsigned h2u(__half2 h) {
    return *reinterpret_cast<unsigned*>(&h);
}
__device__ __forceinline__ void mma_f16(float* d, const unsigned* a,
                                        unsigned b0, unsigned b1) {
    asm volatile("mma.sync.aligned.m16n8k16.row.col.f32.f16.f16.f32 "
                 "{%0,%1,%2,%3}, {%4,%5,%6,%7}, {%8,%9}, {%0,%1,%2,%3};"
                 : "+f"(d[0]), "+f"(d[1]), "+f"(d[2]), "+f"(d[3])
                 : "r"(a[0]), "r"(a[1]), "r"(a[2]), "r"(a[3]), "r"(b0), "r"(b1));
}

// ---------------- K0: zero bins -------------------------------------------------
__global__ void pq_init_kernel(float* __restrict__ outBins) {
    int t = threadIdx.x;
    if (t < N_E) outBins[t] = 0.0f;
}

// ---------------- K_esq: per-code squared norms (mul then sequential add) -------
__global__ void pq_esq_kernel(const float* __restrict__ cbk) {
    int t = blockIdx.x * blockDim.x + threadIdx.x;
    if (t >= M_SUB * N_E) return;
    const float* p = cbk + (size_t)t * E_DIM;
    float s = 0.0f;
    #pragma unroll
    for (int d = 0; d < E_DIM; d++) {
        float v = p[d];
        s = __fadd_rn(s, __fmul_rn(v, v));
    }
    g_esq[t] = s;
}

// ---------------- K_tr: pack codebooks into fp16 fragment order ------------------
__global__ void pq_tr_kernel(const float* __restrict__ cbk) {
    int m  = blockIdx.x >> 4;
    int ch = blockIdx.x & 15;
    int tid = threadIdx.x;
    const float* src = cbk + ((size_t)(m * N_E) + ch * 64) * E_DIM;
    uint2* dst = g_cbh + (size_t)blockIdx.x * 1024;
    #pragma unroll
    for (int it = 0; it < 4; it++) {
        int idx = tid + it * 256;            // 0..1023
        int ks = idx >> 8, nt = (idx >> 5) & 7, gg = (idx >> 2) & 7, lx = idx & 3;
        int c  = nt * 8 + gg;
        int k0 = ks * 16 + 2 * lx;
        const float* r = src + (size_t)c * E_DIM;
        uint2 v;
        v.x = h2u(__floats2half2_rn(r[k0],     r[k0 + 1]));
        v.y = h2u(__floats2half2_rn(r[k0 + 8], r[k0 + 9]));
        dst[idx] = v;
    }
}

// ---------------- K1: fp16 MMA scoring + exact rescore + fused epilogue ---------
// Block 256 threads (8 warps), 3 blocks/SM. Tile: 128 rows x 1024 codes.
// grid = (128, 8). 8 fill phases of 128 codes; two 64-code halves per phase.
// smem carve (floats):
#define S_ZT    0            // z tile [128][65]            (8320)
#define S_CB    8320         // fragment phase 2048 uint2   (4096)
#define S_CAND  12416        // candidates [128][CAP] int   (4096)
#define S_ESQ   16512        // esq                         (1024)
#define S_ZSQ   17536        // zsq                         (128)
#define S_CNT   17664        // counters int                (128)
#define S_WIN   17792        // winners int                 (128)
#define S_RBD   17920        // rescore partial d           (256)
#define S_RBI   18176        // rescore partial idx int     (256)
#define S_TOT   18432        // 73728 bytes -> 3 blocks/SM
#define S_SQ    8320         // gather overlay (8320 <= CB+CAND+ESQ = 9216)

__global__ void __launch_bounds__(256, 3)
pq_dist_kernel(const float* __restrict__ z,
               const float* __restrict__ cbk,
               float* __restrict__ outZvq,
               float* __restrict__ outIdx,
               float* __restrict__ outBins)
{
    extern __shared__ float sm[];
    float*    szt  = sm + S_ZT;
    float*    scb  = sm + S_CB;
    int*      scand= (int*)(sm + S_CAND);
    float*    sesq = sm + S_ESQ;
    float*    szsq = sm + S_ZSQ;
    int*      scnt = (int*)(sm + S_CNT);
    int*      swin = (int*)(sm + S_WIN);
    float*    rbd  = sm + S_RBD;
    int*      rbi  = (int*)(sm + S_RBI);
    __shared__ double swarp[8];

    const int m  = blockIdx.y;
    const int n0 = blockIdx.x * 128;
    const int b  = n0 >> 10;
    const int p0 = n0 & 1023;
    const int tid  = threadIdx.x;
    const int wid  = tid >> 5;
    const int lane = tid & 31;
    const int gg   = lane >> 2;      // group id 0..7
    const int lx   = lane & 3;       // thread-in-group
    const int row0 = wid * 16 + gg;  // rows owned by this thread's D frags (warp-excl.)
    const float INFF = __int_as_float(0x7f800000);

    // ---- load z tile [pos][d] (transpose from gmem [d][pos]) ----
    const float* zbase = z + ((size_t)(b * CC_ + m * E_DIM) * HW_) + p0;
    #pragma unroll
    for (int it = 0; it < 8; it++) {
        int i = tid + it * 256;
        int d = i >> 5, j4 = (i & 31) * 4;
        float4 v = *(const float4*)(zbase + (size_t)d * HW_ + j4);
        szt[(j4 + 0) * 65 + d] = v.x;
        szt[(j4 + 1) * 65 + d] = v.y;
        szt[(j4 + 2) * 65 + d] = v.z;
        szt[(j4 + 3) * 65 + d] = v.w;
    }
    #pragma unroll
    for (int it = 0; it < 4; it++)
        sesq[tid + it * 256] = g_esq[m * N_E + tid + it * 256];
    if (tid < 128) scnt[tid] = 0;
    __syncthreads();

    // ---- per-row ||z||^2 (sequential chain, matches reference) ----
    if (tid < 128) {
        float s = 0.0f;
        const float* zr = szt + tid * 65;
        #pragma unroll
        for (int k = 0; k < E_DIM; k++)
            s = __fadd_rn(s, __fmul_rn(zr[k], zr[k]));
        szsq[tid] = s;
    }

    // ---- A fragments fp16 (held in regs): rows row0/row0+8, k=64 ----
    unsigned afr[4][4];
    {
        const float* zr0 = szt + row0 * 65;
        const float* zr1 = szt + (row0 + 8) * 65;
        #pragma unroll
        for (int ks = 0; ks < 4; ks++) {
            int k0 = 16 * ks + 2 * lx;
            afr[ks][0] = h2u(__floats2half2_rn(zr0[k0],     zr0[k0 + 1]));
            afr[ks][1] = h2u(__floats2half2_rn(zr1[k0],     zr1[k0 + 1]));
            afr[ks][2] = h2u(__floats2half2_rn(zr0[k0 + 8], zr0[k0 + 9]));
            afr[ks][3] = h2u(__floats2half2_rn(zr1[k0 + 8], zr1[k0 + 9]));
        }
    }

    // ---- 8 phases of 128 codes; two 64-code halves per phase --------------------
    const uint2* ctb = g_cbh + (size_t)m * 16384;   // 16 chunks x 1024 uint2
    float rmin0 = INFF, rmin1 = INFF;       // register prefix minima (rows warp-excl.)
    for (int ph = 0; ph < 8; ph++) {
        __syncthreads();   // prev phase fully consumed
        // fill 2 fragment chunks = 2048 uint2 = 16KB (contiguous copy)
        {
            const uint4* g4 = (const uint4*)(ctb + ph * 2048);
            uint4* s4 = (uint4*)scb;
            #pragma unroll
            for (int it = 0; it < 4; it++)
                s4[tid + it * 256] = g4[tid + it * 256];
        }
        __syncthreads();   // phase ready

        #pragma unroll
        for (int h = 0; h < 2; h++) {
            float acc[8][4];
            #pragma unroll
            for (int nt = 0; nt < 8; nt++)
                #pragma unroll
                for (int q = 0; q < 4; q++) acc[nt][q] = 0.0f;

            // conflict-free: per (ks,nt) a warp reads one contiguous 256B span
            const uint2* bp = (const uint2*)scb + h * 1024 + gg * 4 + lx;
            #pragma unroll
            for (int ks = 0; ks < 4; ks++) {
                #pragma unroll
                for (int nt = 0; nt < 8; nt++) {
                    uint2 bb = bp[ks * 256 + nt * 32];
                    mma_f16(acc[nt], afr[ks], bb.x, bb.y);
                }
            }

            // pass 1: scores esq[c] - 2*dot, cached IN PLACE into acc; chunk min
            const int cbase = ph * 128 + h * 64;
            float m0 = INFF, m1 = INFF;
            #pragma unroll
            for (int nt = 0; nt < 8; nt++) {
                int c = cbase + nt * 8 + 2 * lx;
                float2 e = *(const float2*)(sesq + c);
                float s0 = __fmaf_rn(acc[nt][0], -2.0f, e.x);
                float s1 = __fmaf_rn(acc[nt][1], -2.0f, e.y);
                float s2 = __fmaf_rn(acc[nt][2], -2.0f, e.x);
                float s3 = __fmaf_rn(acc[nt][3], -2.0f, e.y);
                acc[nt][0] = s0; acc[nt][1] = s1; acc[nt][2] = s2; acc[nt][3] = s3;
                m0 = fminf(m0, fminf(s0, s1));
                m1 = fminf(m1, fminf(s2, s3));
            }
            #pragma unroll
            for (int off = 1; off <= 2; off <<= 1) {
                m0 = fminf(m0, __shfl_xor_sync(0xffffffffu, m0, off));
                m1 = fminf(m1, __shfl_xor_sync(0xffffffffu, m1, off));
            }
            // rows are warp-exclusive: register prefix-min is the exact row min
            rmin0 = fminf(rmin0, m0);
            rmin1 = fminf(rmin1, m1);
            float thr0 = rmin0 + EPSF;
            float thr1 = rmin1 + EPSF;

            // pass 2: collect (scores read from acc; thresholds incl. this half)
            #pragma unroll
            for (int nt = 0; nt < 8; nt++) {
                int c = cbase + nt * 8 + 2 * lx;
                if (acc[nt][0] <= thr0) { int p = atomicAdd(scnt + row0, 1);     if (p < CAP) scand[row0 * CAP + p] = c; }
                if (acc[nt][1] <= thr0) { int p = atomicAdd(scnt + row0, 1);     if (p < CAP) scand[row0 * CAP + p] = c + 1; }
                if (acc[nt][2] <= thr1) { int p = atomicAdd(scnt + row0 + 8, 1); if (p < CAP) scand[(row0 + 8) * CAP + p] = c; }
                if (acc[nt][3] <= thr1) { int p = atomicAdd(scnt + row0 + 8, 1); if (p < CAP) scand[(row0 + 8) * CAP + p] = c + 1; }
            }
        }
    }
    __syncthreads();

    // ---- exact rescore (reference-identical fp32 chains); 2 threads per row ----
    {
        int row = (tid < 128) ? tid : tid - 128;
        int start = (tid < 128) ? 0 : 1;
        int cnt = scnt[row];
        const float* zr = szt + row * 65;
        float zsqv = szsq[row];
        const float* cbm = cbk + (size_t)m * N_E * E_DIM;
        float bd = INFF; int bi = 0x7fffffff;

        auto exact_d = [&](int c) -> float {
            const float* cr = cbm + (size_t)c * E_DIM;
            float s = 0.0f;
            #pragma unroll
            for (int g4 = 0; g4 < 4; g4++) {
                float4 c0 = *(const float4*)(cr + g4 * 16);
                float4 c1 = *(const float4*)(cr + g4 * 16 + 4);
                float4 c2 = *(const float4*)(cr + g4 * 16 + 8);
                float4 c3 = *(const float4*)(cr + g4 * 16 + 12);
                const float* zp = zr + g4 * 16;
                s = __fmaf_rn(zp[0],  c0.x, s); s = __fmaf_rn(zp[1],  c0.y, s);
                s = __fmaf_rn(zp[2],  c0.z, s); s = __fmaf_rn(zp[3],  c0.w, s);
                s = __fmaf_rn(zp[4],  c1.x, s); s = __fmaf_rn(zp[5],  c1.y, s);
                s = __fmaf_rn(zp[6],  c1.z, s); s = __fmaf_rn(zp[7],  c1.w, s);
                s = __fmaf_rn(zp[8],  c2.x, s); s = __fmaf_rn(zp[9],  c2.y, s);
                s = __fmaf_rn(zp[10], c2.z, s); s = __fmaf_rn(zp[11], c2.w, s);
                s = __fmaf_rn(zp[12], c3.x, s); s = __fmaf_rn(zp[13], c3.y, s);
                s = __fmaf_rn(zp[14], c3.z, s); s = __fmaf_rn(zp[15], c3.w, s);
            }
            return __fsub_rn(__fadd_rn(zsqv, sesq[c]), __fmul_rn(2.0f, s));
        };

        if (cnt <= CAP) {
            for (int i = start; i < cnt; i += 2) {
                int c = scand[row * CAP + i];
                float d = exact_d(c);
                if (d < bd || (d == bd && c < bi)) { bd = d; bi = c; }
            }
        } else {  // overflow fallback: full exact scan (provably correct, ~never)
            for (int c = start; c < N_E; c += 2) {
                float d = exact_d(c);
                if (d < bd || (d == bd && c < bi)) { bd = d; bi = c; }
            }
        }
        rbd[tid] = bd; rbi[tid] = bi;
    }
    __syncthreads();
    if (tid < 128) {
        float bd = rbd[tid]; int bi = rbi[tid];
        float d2 = rbd[tid + 128]; int i2 = rbi[tid + 128];
        if (d2 < bd || (d2 == bd && i2 < bi)) { bd = d2; bi = i2; }
        swin[tid] = bi;
        outIdx[m * NPOS + n0 + tid] = (float)bi;
        atomicAdd(outBins + bi, 1.0f);   // integer-valued float adds: exact
    }
    __syncthreads();

    // ---- gather winning code rows into sq[row][d], stride 65 (overlay) ----
    float* sq = sm + S_SQ;
    const float* cbm = cbk + (size_t)m * N_E * E_DIM;
    #pragma unroll
    for (int it = 0; it < 8; it++) {
        int i = tid + it * 256;
        int row = i >> 4, d4 = (i & 15) * 4;
        int idx = swin[row];
        float4 v = *(const float4*)(cbm + (size_t)idx * E_DIM + d4);
        float* dp = sq + row * 65 + d4;
        dp[0] = v.x; dp[1] = v.y; dp[2] = v.z; dp[3] = v.w;
    }
    __syncthreads();

    // ---- z_vq = zf + (zq - zf); loss partial in double ----
    double lsum = 0.0;
    float* ob = outZvq + ((size_t)(b * CC_ + m * E_DIM)) * HW_ + p0;
    #pragma unroll
    for (int it = 0; it < 8; it++) {
        int i = tid + it * 256;
        int d = i >> 5, j4 = (i & 31) * 4;
        float o[4];
        #pragma unroll
        for (int q = 0; q < 4; q++) {
            float zf = szt[(j4 + q) * 65 + d];
            float zq = sq[(j4 + q) * 65 + d];
            float df = __fsub_rn(zq, zf);
            o[q] = __fadd_rn(zf, df);
            lsum += (double)df * (double)df;
        }
        *(float4*)(ob + (size_t)d * HW_ + j4) = make_float4(o[0], o[1], o[2], o[3]);
    }

    #pragma unroll
    for (int off = 16; off > 0; off >>= 1)
        lsum += __shfl_down_sync(0xffffffffu, lsum, off);
    if (lane == 0) swarp[wid] = lsum;
    __syncthreads();
    if (wid == 0) {
        double v = (lane < 8) ? swarp[lane] : 0.0;
        #pragma unroll
        for (int off = 4; off > 0; off >>= 1)
            v += __shfl_down_sync(0xffffffffu, v, off);
        if (lane == 0) g_part[m * 128 + blockIdx.x] = v;
    }
}

// ---------------- K3: finalize loss ---------------------------------------------
__global__ void pq_loss_kernel(float* __restrict__ outLoss) {
    __shared__ double sred[256];
    int t = threadIdx.x;
    double s = 0.0;
    for (int i = t; i < 1024; i += 256) s += g_part[i];
    sred[t] = s;
    __syncthreads();
    for (int off = 128; off > 0; off >>= 1) {
        if (t < off) sred[t] += sred[t + off];
        __syncthreads();
    }
    if (t == 0) {
        double loss = 1.25 * sred[0] / (double)((size_t)NPOS * E_DIM);
        outLoss[0] = (float)loss;
    }
}

// ---------------- launch ----------------------------------------------------------
extern "C" void kernel_launch(void* const* d_in, const int* in_sizes, int n_in,
                              void* d_out, int out_size)
{
    const float* z   = (const float*)d_in[0];
    const float* cbk = (const float*)d_in[1];
    if (n_in >= 2 && in_sizes[0] == M_SUB * N_E * E_DIM) {  // swapped-order safety
        z   = (const float*)d_in[1];
        cbk = (const float*)d_in[0];
    }
    float* out = (float*)d_out;
    float* outZvq  = out + OFF_ZVQ;
    float* outLoss = out + OFF_LOSS;
    float* outIdx  = out + OFF_IDX;
    float* outBins = out + OFF_BIN;

    const int dyn_smem = S_TOT * 4;   // 73728 B -> 3 blocks/SM
    cudaFuncSetAttribute(pq_dist_kernel,
                         cudaFuncAttributeMaxDynamicSharedMemorySize, dyn_smem);

    pq_init_kernel<<<1, 1024>>>(outBins);
    pq_esq_kernel<<<(M_SUB * N_E + 255) / 256, 256>>>(cbk);
    pq_tr_kernel<<<128, 256>>>(cbk);
    dim3 g1(NPOS / 128, M_SUB);
    pq_dist_kernel<<<g1, 256, dyn_smem>>>(z, cbk, outZvq, outIdx, outBins);
    pq_loss_kernel<<<1, 256>>>(outLoss);
}